// round 6
// baseline (speedup 1.0000x reference)
#include <cuda_runtime.h>
#include <math.h>

#define BB   32
#define LQ   512
#define DD   384
#define FF   384
#define MROWS (BB*LQ)      // 16384
#define KDIM  (DD*3)       // 1152
#define LN_EPS 1e-5f
#define STAGES 3
#define ROWSTRIDE 24

// Scratch (no allocations allowed).
__device__ float g_buf1[(size_t)MROWS * FF];
__device__ float g_buf2[(size_t)MROWS * FF];
__device__ float g_xp  [(size_t)MROWS * DD];
__device__ float g_w1r[(size_t)FF * KDIM];
__device__ float g_w2r[(size_t)FF * KDIM];
__device__ int   g_cum[BB * LQ];

// Pair-permutation within each 16-element K block (k and k+4 adjacent -> LDS.64)
__device__ __forceinline__ int perm16(int j)
{
    return (j < 4) ? 2 * j
         : (j < 8) ? 2 * (j - 4) + 1
         : (j < 12) ? 2 * (j - 8) + 8
                    : 2 * (j - 12) + 9;
}

__device__ __forceinline__ unsigned f2tf(float f)
{
    unsigned r;
    asm("cvt.rna.tf32.f32 %0, %1;" : "=r"(r) : "f"(f));
    return r;
}

__global__ __launch_bounds__(256) void prep_x_kernel(
    const float* __restrict__ in, float* __restrict__ out)
{
    const int idx = blockIdx.x * 256 + threadIdx.x;
    const int row = idx / DD;
    const int col = idx - row * DD;
    const int blk = col >> 4, j = col & 15;
    out[(size_t)row * DD + (blk << 4) + perm16(j)] = __uint_as_float(f2tf(in[idx]));
}

// Both weights in one launch: blockIdx.y selects (src,dst) pair.
__global__ __launch_bounds__(256) void reorder_w2_kernel(
    const float* __restrict__ W1, float* __restrict__ Wr1,
    const float* __restrict__ W2, float* __restrict__ Wr2)
{
    const float* W  = blockIdx.y ? W2 : W1;
    float*       Wr = blockIdx.y ? Wr2 : Wr1;
    const int f = blockIdx.x;
    for (int i = threadIdx.x; i < KDIM; i += 256) {
        const int kseg = i / DD;
        const int r    = i - kseg * DD;
        const int blk  = r >> 4, j = r & 15;
        const int dst  = kseg * DD + (blk << 4) + perm16(j);
        Wr[(size_t)f * KDIM + dst] =
            __uint_as_float(f2tf(W[(size_t)f * KDIM + (blk * 16 + j) * 3 + kseg]));
    }
}

__device__ __forceinline__ void mma_tf32(float c[4], const unsigned a[4],
                                         const unsigned b[2])
{
    asm volatile(
        "mma.sync.aligned.m16n8k8.row.col.f32.tf32.tf32.f32 "
        "{%0,%1,%2,%3}, {%4,%5,%6,%7}, {%8,%9}, {%0,%1,%2,%3};"
        : "+f"(c[0]), "+f"(c[1]), "+f"(c[2]), "+f"(c[3])
        : "r"(a[0]), "r"(a[1]), "r"(a[2]), "r"(a[3]), "r"(b[0]), "r"(b[1]));
}

__device__ __forceinline__ void cp16(unsigned dst, const float* src, bool p)
{
    const int sz = p ? 16 : 0;
    asm volatile("cp.async.cg.shared.global [%0], [%1], 16, %2;\n"
                 :: "r"(dst), "l"(src), "r"(sz));
}

// ---------------------------------------------------------------------------
// Conv-as-GEMM, tf32 mma.sync. CTA tile 128(M) x 64(N), BK=16, 128 threads,
// 4 warps in 2x2 (warp tile 64x32 -- same inner loop as the proven config).
// 3-stage cp.async pipeline; 4 CTAs/SM; grid 768 kills wave quantization.
// ---------------------------------------------------------------------------
__global__ __launch_bounds__(128, 4) void conv_mma_kernel(
    const float* __restrict__ Asrc, const float* __restrict__ Wr,
    const float* __restrict__ bias, float* __restrict__ Y)
{
    extern __shared__ float sm[];
    float* As = sm;                              // [STAGES][128][24]
    float* Bs = sm + STAGES * 128 * ROWSTRIDE;   // [STAGES][64][24]

    const int m0 = blockIdx.x * 128;
    const int f0 = blockIdx.y * 64;
    const int t  = threadIdx.x;
    const int lane = t & 31, grp = lane >> 2, tig = lane & 3;
    const int warp = t >> 5;                 // 0..3
    const int m_base = (warp & 1) * 64;
    const int n_base = (warp >> 1) * 32;

    const int lrow = t >> 2;            // 0..31
    const int c4   = (t & 3) * 4;       // 0,4,8,12

    int bA[4], lA[4];
    #pragma unroll
    for (int rr = 0; rr < 4; ++rr) {
        const int m = m0 + lrow + rr * 32;
        bA[rr] = m >> 9;
        lA[rr] = m & 511;
    }

    const unsigned aAd0 = (unsigned)__cvta_generic_to_shared(&As[lrow * ROWSTRIDE + c4]);
    const unsigned bAd0 = (unsigned)__cvta_generic_to_shared(&Bs[lrow * ROWSTRIDE + c4]);
    const unsigned STB_A = 128 * ROWSTRIDE * 4;
    const unsigned STB_B = 64 * ROWSTRIDE * 4;
    const unsigned ROW32 = 32 * ROWSTRIDE * 4;

    const float* wr0 = Wr + (size_t)(f0 + lrow) * KDIM + c4;
    const float* wr1 = Wr + (size_t)(f0 + lrow + 32) * KDIM + c4;

    float acc[4][4][4] = {};

    auto load_tile = [&](int it, int st) {
        const int kk0  = it * 16;
        const int kseg = (kk0 >= 384) + (kk0 >= 768);
        const int off  = kk0 - kseg * DD + c4;
        #pragma unroll
        for (int rr = 0; rr < 4; ++rr) {
            const int l2 = lA[rr] + kseg - 1;
            const bool v = (l2 >= 0) & (l2 < LQ);
            const float* sa = Asrc + ((size_t)(bA[rr] << 9) + (v ? l2 : 0)) * DD + off;
            cp16(aAd0 + st * STB_A + rr * ROW32, sa, v);
        }
        cp16(bAd0 + st * STB_B,         wr0 + kk0, true);
        cp16(bAd0 + st * STB_B + ROW32, wr1 + kk0, true);
    };

    load_tile(0, 0);
    asm volatile("cp.async.commit_group;");
    load_tile(1, 1);
    asm volatile("cp.async.commit_group;");
    asm volatile("cp.async.wait_group 1;");
    __syncthreads();

    const int NIT = KDIM / 16;   // 72
    int st_next = 2, buf = 0;
    for (int it = 0; it < NIT; ++it) {
        if (it + 2 < NIT) load_tile(it + 2, st_next);
        asm volatile("cp.async.commit_group;");
        if (++st_next == STAGES) st_next = 0;

        const float* Ab = As + buf * 128 * ROWSTRIDE;
        const float* Bb = Bs + buf * 64 * ROWSTRIDE;
        #pragma unroll
        for (int ks = 0; ks < 2; ++ks) {
            const int pc = ks * 8 + 2 * tig;
            float2 bf[4];
            #pragma unroll
            for (int nt = 0; nt < 4; ++nt)
                bf[nt] = *(const float2*)&Bb[(n_base + nt * 8 + grp) * ROWSTRIDE + pc];
            #pragma unroll
            for (int mt = 0; mt < 4; ++mt) {
                const int ar = m_base + mt * 16 + grp;
                const float2 a02 = *(const float2*)&Ab[ar * ROWSTRIDE + pc];
                const float2 a13 = *(const float2*)&Ab[(ar + 8) * ROWSTRIDE + pc];
                const unsigned af[4] = {
                    __float_as_uint(a02.x), __float_as_uint(a13.x),
                    __float_as_uint(a02.y), __float_as_uint(a13.y) };
                #pragma unroll
                for (int nt = 0; nt < 4; ++nt) {
                    const unsigned bb[2] = { __float_as_uint(bf[nt].x),
                                             __float_as_uint(bf[nt].y) };
                    mma_tf32(acc[mt][nt], af, bb);
                }
            }
        }
        if (++buf == STAGES) buf = 0;

        asm volatile("cp.async.wait_group 1;");
        __syncthreads();
    }

    #pragma unroll
    for (int mt = 0; mt < 4; ++mt) {
        const int mrow = m0 + m_base + mt * 16 + grp;
        #pragma unroll
        for (int nt = 0; nt < 4; ++nt) {
            const int fc = f0 + n_base + nt * 8 + 2 * tig;
            const float b0v = bias[fc], b1v = bias[fc + 1];
            float2 r0 = make_float2(acc[mt][nt][0] + b0v, acc[mt][nt][1] + b1v);
            float2 r1 = make_float2(acc[mt][nt][2] + b0v, acc[mt][nt][3] + b1v);
            *(float2*)&Y[(size_t)mrow * FF + fc] = r0;
            *(float2*)&Y[(size_t)(mrow + 8) * FF + fc] = r1;
        }
    }
}

// ---------------------------------------------------------------------------
__device__ __forceinline__ float2 block_reduce2(float s, float q)
{
    __shared__ float sh[8];
    __syncthreads();
    const int lane = threadIdx.x & 31;
    const int w    = threadIdx.x >> 5;
    #pragma unroll
    for (int o = 16; o > 0; o >>= 1) {
        s += __shfl_down_sync(0xffffffffu, s, o);
        q += __shfl_down_sync(0xffffffffu, q, o);
    }
    if (lane == 0) { sh[w] = s; sh[4 + w] = q; }
    __syncthreads();
    if (threadIdx.x == 0) {
        sh[0] = sh[0] + sh[1] + sh[2] + sh[3];
        sh[4] = sh[4] + sh[5] + sh[6] + sh[7];
    }
    __syncthreads();
    return make_float2(sh[0], sh[4]);
}

__global__ __launch_bounds__(128) void ln_relu_kernel(
    const float* __restrict__ In, const float* __restrict__ gam,
    const float* __restrict__ bet, float* __restrict__ Out)
{
    const int row = blockIdx.x;
    const int t   = threadIdx.x;
    const float* p = In + (size_t)row * FF;
    float v0 = p[t], v1 = p[t + 128], v2 = p[t + 256];
    float2 r = block_reduce2(v0 + v1 + v2, v0 * v0 + v1 * v1 + v2 * v2);
    const float mu  = r.x * (1.0f / FF);
    const float var = r.y * (1.0f / FF) - mu * mu;
    const float rs  = rsqrtf(var + LN_EPS);
    float* o = Out + (size_t)row * FF;
    float v[3] = {v0, v1, v2};
    #pragma unroll
    for (int i = 0; i < 3; i++) {
        const int f = t + i * 128;
        const float h = fmaxf((v[i] - mu) * rs * gam[f] + bet[f], 0.0f);
        const int blk = f >> 4, j = f & 15;
        o[(blk << 4) + perm16(j)] = __uint_as_float(f2tf(h));
    }
}

__global__ __launch_bounds__(128) void ln_linear_kernel(
    const float* __restrict__ In, const float* __restrict__ gam,
    const float* __restrict__ bet, const float* __restrict__ lw,
    const float* __restrict__ lb, float* __restrict__ dur)
{
    const int row = blockIdx.x;
    const int t   = threadIdx.x;
    const float* p = In + (size_t)row * FF;
    float v0 = p[t], v1 = p[t + 128], v2 = p[t + 256];
    float2 r = block_reduce2(v0 + v1 + v2, v0 * v0 + v1 * v1 + v2 * v2);
    const float mu  = r.x * (1.0f / FF);
    const float var = r.y * (1.0f / FF) - mu * mu;
    const float rs  = rsqrtf(var + LN_EPS);
    float v[3] = {v0, v1, v2};
    float acc = 0.0f;
    #pragma unroll
    for (int i = 0; i < 3; i++) {
        const int f = t + i * 128;
        float h = fmaxf((v[i] - mu) * rs * gam[f] + bet[f], 0.0f);
        acc += h * lw[f];
    }
    float2 r2 = block_reduce2(acc, 0.0f);
    if (t == 0) dur[row] = fmaxf(r2.x + lb[0], 0.0f);
}

__global__ __launch_bounds__(512) void scan_kernel(const int* __restrict__ target)
{
    __shared__ int s[512];
    const int b = blockIdx.x, t = threadIdx.x;
    s[t] = target[b * LQ + t];
    __syncthreads();
    for (int off = 1; off < 512; off <<= 1) {
        int v = (t >= off) ? s[t - off] : 0;
        __syncthreads();
        s[t] += v;
        __syncthreads();
    }
    g_cum[b * LQ + t] = s[t];
}

__global__ __launch_bounds__(384) void expand_kernel(
    const float* __restrict__ X, float* __restrict__ out, int M)
{
    const int tfr = blockIdx.x * 4 + threadIdx.y;
    const int b   = blockIdx.y;
    const int* cum = g_cum + b * LQ;
    float4* dst = (float4*)(out + ((size_t)b * M + tfr) * DD);
    const int total = cum[LQ - 1];
    if (tfr >= total) {
        dst[threadIdx.x] = make_float4(0.f, 0.f, 0.f, 0.f);
        return;
    }
    int lo = 0, hi = LQ;
    while (lo < hi) {
        int mid = (lo + hi) >> 1;
        if (cum[mid] <= tfr) lo = mid + 1; else hi = mid;
    }
    const int idx = min(lo, LQ - 1);
    const float4* src = (const float4*)(X + ((size_t)b * LQ + idx) * DD);
    dst[threadIdx.x] = src[threadIdx.x];
}

// ---------------------------------------------------------------------------
extern "C" void kernel_launch(void* const* d_in, const int* in_sizes, int n_in,
                              void* d_out, int out_size)
{
    const float* x     = (const float*)d_in[0];
    const float* c1_w  = (const float*)d_in[1];
    const float* c1_b  = (const float*)d_in[2];
    const float* ln1_g = (const float*)d_in[3];
    const float* ln1_b = (const float*)d_in[4];
    const float* c2_w  = (const float*)d_in[5];
    const float* c2_b  = (const float*)d_in[6];
    const float* ln2_g = (const float*)d_in[7];
    const float* ln2_b = (const float*)d_in[8];
    const float* lin_w = (const float*)d_in[9];
    const float* lin_b = (const float*)d_in[10];
    const int*   target= (const int*)d_in[11];

    const int M = (out_size - BB * LQ) / (BB * DD);

    float* buf1; cudaGetSymbolAddress((void**)&buf1, g_buf1);
    float* buf2; cudaGetSymbolAddress((void**)&buf2, g_buf2);
    float* xp;   cudaGetSymbolAddress((void**)&xp,   g_xp);
    float* w1r;  cudaGetSymbolAddress((void**)&w1r,  g_w1r);
    float* w2r;  cudaGetSymbolAddress((void**)&w2r,  g_w2r);

    float* out_expand = (float*)d_out;
    float* out_dur    = (float*)d_out + (size_t)BB * M * DD;

    const int smem_bytes = STAGES * (128 + 64) * ROWSTRIDE * 4;  // 55296
    cudaFuncSetAttribute(conv_mma_kernel,
                         cudaFuncAttributeMaxDynamicSharedMemorySize, smem_bytes);

    // Fork: scan+expand are independent of the predictor chain.
    cudaStream_t s2;
    cudaStreamCreateWithFlags(&s2, cudaStreamNonBlocking);
    cudaEvent_t ev_fork, ev_join;
    cudaEventCreateWithFlags(&ev_fork, cudaEventDisableTiming);
    cudaEventCreateWithFlags(&ev_join, cudaEventDisableTiming);

    cudaEventRecord(ev_fork, 0);
    cudaStreamWaitEvent(s2, ev_fork, 0);
    scan_kernel<<<BB, 512, 0, s2>>>(target);
    expand_kernel<<<dim3(M / 4, BB), dim3(96, 4), 0, s2>>>(x, out_expand, M);
    cudaEventRecord(ev_join, s2);

    // Predictor chain
    dim3 gemm_grid(MROWS / 128, FF / 64);
    prep_x_kernel<<<MROWS * DD / 256, 256>>>(x, xp);
    reorder_w2_kernel<<<dim3(FF, 2), 256>>>(c1_w, w1r, c2_w, w2r);
    conv_mma_kernel<<<gemm_grid, 128, smem_bytes>>>(xp, w1r, c1_b, buf1);
    ln_relu_kernel<<<MROWS, 128>>>(buf1, ln1_g, ln1_b, buf2);
    conv_mma_kernel<<<gemm_grid, 128, smem_bytes>>>(buf2, w2r, c2_b, buf1);
    ln_linear_kernel<<<MROWS, 128>>>(buf1, ln2_g, ln2_b, lin_w, lin_b, out_dur);

    cudaStreamWaitEvent(0, ev_join, 0);
}

// round 8
// speedup vs baseline: 1.0120x; 1.0120x over previous
#include <cuda_runtime.h>
#include <math.h>

#define BB   32
#define LQ   512
#define DD   384
#define FF   384
#define MROWS (BB*LQ)      // 16384
#define KDIM  (DD*3)       // 1152
#define LN_EPS 1e-5f
#define STAGES 3
#define ROWSTRIDE 24
#define GEMM_BLOCKS ((MROWS/128)*(FF/64))   // 768
#define NPX (MROWS*DD/256)                  // 24576 prep_x blocks
#define NWR (FF*2)                          // 768 reorder blocks

// Scratch (no allocations allowed).
__device__ float g_buf1[(size_t)MROWS * FF];
__device__ float g_buf2[(size_t)MROWS * FF];
__device__ float g_xp  [(size_t)MROWS * DD];
__device__ float g_w1r[(size_t)FF * KDIM];
__device__ float g_w2r[(size_t)FF * KDIM];
__device__ int   g_cum[BB * LQ];

// Pair-permutation within each 16-element K block (k and k+4 adjacent -> LDS.64)
__device__ __forceinline__ int perm16(int j)
{
    return (j < 4) ? 2 * j
         : (j < 8) ? 2 * (j - 4) + 1
         : (j < 12) ? 2 * (j - 8) + 8
                    : 2 * (j - 12) + 9;
}

__device__ __forceinline__ unsigned f2tf(float f)
{
    unsigned r;
    asm("cvt.rna.tf32.f32 %0, %1;" : "=r"(r) : "f"(f));
    return r;
}

// ---------------------------------------------------------------------------
// Fused prep: [0,NPX) x round+permute ; [NPX,NPX+NWR) weight reorder ;
// [NPX+NWR, NPX+NWR+BB) cumsum scan.  256 threads everywhere.
// ---------------------------------------------------------------------------
__global__ __launch_bounds__(256) void prep_all_kernel(
    const float* __restrict__ x, float* __restrict__ xp,
    const float* __restrict__ W1, float* __restrict__ Wr1,
    const float* __restrict__ W2, float* __restrict__ Wr2,
    const int* __restrict__ target)
{
    const int bidx = blockIdx.x;
    const int t = threadIdx.x;

    if (bidx < NPX) {
        const int idx = bidx * 256 + t;
        const int row = idx / DD;
        const int col = idx - row * DD;
        const int blk = col >> 4, j = col & 15;
        xp[(size_t)row * DD + (blk << 4) + perm16(j)] =
            __uint_as_float(f2tf(x[idx]));
    } else if (bidx < NPX + NWR) {
        const int r2 = bidx - NPX;
        const float* W  = (r2 >= FF) ? W2 : W1;
        float*       Wr = (r2 >= FF) ? Wr2 : Wr1;
        const int f = (r2 >= FF) ? r2 - FF : r2;
        for (int i = t; i < KDIM; i += 256) {
            const int kseg = i / DD;
            const int r    = i - kseg * DD;
            const int blk  = r >> 4, j = r & 15;
            const int dst  = kseg * DD + (blk << 4) + perm16(j);
            Wr[(size_t)f * KDIM + dst] =
                __uint_as_float(f2tf(W[(size_t)f * KDIM + (blk * 16 + j) * 3 + kseg]));
        }
    } else {
        // inclusive scan of 512 durations, 256 threads (2 elems/thread)
        __shared__ int s[512];
        const int b = bidx - (NPX + NWR);
        s[t]       = target[b * LQ + t];
        s[t + 256] = target[b * LQ + t + 256];
        __syncthreads();
        for (int off = 1; off < 512; off <<= 1) {
            const int v0 = (t >= off) ? s[t - off] : 0;
            const int v1 = s[t + 256 - off];          // t+256 >= off always (off<512)
            __syncthreads();
            s[t] += v0;
            s[t + 256] += v1;
            __syncthreads();
        }
        g_cum[b * LQ + t]       = s[t];
        g_cum[b * LQ + t + 256] = s[t + 256];
    }
}

__device__ __forceinline__ void mma_tf32(float c[4], const unsigned a[4],
                                         const unsigned b[2])
{
    asm volatile(
        "mma.sync.aligned.m16n8k8.row.col.f32.tf32.tf32.f32 "
        "{%0,%1,%2,%3}, {%4,%5,%6,%7}, {%8,%9}, {%0,%1,%2,%3};"
        : "+f"(c[0]), "+f"(c[1]), "+f"(c[2]), "+f"(c[3])
        : "r"(a[0]), "r"(a[1]), "r"(a[2]), "r"(a[3]), "r"(b[0]), "r"(b[1]));
}

__device__ __forceinline__ void cp16(unsigned dst, const float* src, bool p)
{
    const int sz = p ? 16 : 0;
    asm volatile("cp.async.cg.shared.global [%0], [%1], 16, %2;\n"
                 :: "r"(dst), "l"(src), "r"(sz));
}

// ---------------------------------------------------------------------------
// Fused conv + expand. Blocks [0, GEMM_BLOCKS): tf32 mma conv (tile 128x64,
// 3-stage cp.async, unchanged). Blocks >= GEMM_BLOCKS: expand frame-groups
// (8 frames each, 96 float4 lanes) that fill the conv's idle wave-2 slots.
// ---------------------------------------------------------------------------
__global__ __launch_bounds__(128, 4) void conv_expand_kernel(
    const float* __restrict__ Asrc, const float* __restrict__ Wr,
    const float* __restrict__ bias, float* __restrict__ Y,
    const float* __restrict__ X, float* __restrict__ out,
    int M, int exp_base)
{
    if (blockIdx.x >= GEMM_BLOCKS) {
        // ---------------- expand ----------------
        if (threadIdx.x < 96) {
            const int g   = blockIdx.x - GEMM_BLOCKS + exp_base;
            const int gpb = M >> 3;                 // groups per batch
            const int b   = g / gpb;
            const int fg  = g - b * gpb;
            const int* cum = g_cum + b * LQ;
            const int total = __ldg(&cum[LQ - 1]);
            #pragma unroll
            for (int i = 0; i < 8; ++i) {
                const int tfr = fg * 8 + i;
                float4* dst = (float4*)(out + ((size_t)b * M + tfr) * DD);
                if (tfr >= total) {
                    __stcs(&dst[threadIdx.x], make_float4(0.f, 0.f, 0.f, 0.f));
                } else {
                    int lo = 0, hi = LQ;
                    while (lo < hi) {
                        const int mid = (lo + hi) >> 1;
                        if (__ldg(&cum[mid]) <= tfr) lo = mid + 1; else hi = mid;
                    }
                    const int idx = min(lo, LQ - 1);
                    const float4* src = (const float4*)(X + ((size_t)b * LQ + idx) * DD);
                    __stcs(&dst[threadIdx.x], __ldg(&src[threadIdx.x]));
                }
            }
        }
        return;
    }

    // ---------------- conv (proven config) ----------------
    extern __shared__ float sm[];
    float* As = sm;
    float* Bs = sm + STAGES * 128 * ROWSTRIDE;

    const int m0 = (blockIdx.x & 127) * 128;    // 128 m-tiles
    const int f0 = (blockIdx.x >> 7) * 64;      // 6 f-tiles
    const int t  = threadIdx.x;
    const int lane = t & 31, grp = lane >> 2, tig = lane & 3;
    const int warp = t >> 5;
    const int m_base = (warp & 1) * 64;
    const int n_base = (warp >> 1) * 32;

    const int lrow = t >> 2;
    const int c4   = (t & 3) * 4;

    int bA[4], lA[4];
    #pragma unroll
    for (int rr = 0; rr < 4; ++rr) {
        const int m = m0 + lrow + rr * 32;
        bA[rr] = m >> 9;
        lA[rr] = m & 511;
    }

    const unsigned aAd0 = (unsigned)__cvta_generic_to_shared(&As[lrow * ROWSTRIDE + c4]);
    const unsigned bAd0 = (unsigned)__cvta_generic_to_shared(&Bs[lrow * ROWSTRIDE + c4]);
    const unsigned STB_A = 128 * ROWSTRIDE * 4;
    const unsigned STB_B = 64 * ROWSTRIDE * 4;
    const unsigned ROW32 = 32 * ROWSTRIDE * 4;

    const float* wr0 = Wr + (size_t)(f0 + lrow) * KDIM + c4;
    const float* wr1 = Wr + (size_t)(f0 + lrow + 32) * KDIM + c4;

    float acc[4][4][4] = {};

    auto load_tile = [&](int it, int st) {
        const int kk0  = it * 16;
        const int kseg = (kk0 >= 384) + (kk0 >= 768);
        const int off  = kk0 - kseg * DD + c4;
        #pragma unroll
        for (int rr = 0; rr < 4; ++rr) {
            const int l2 = lA[rr] + kseg - 1;
            const bool v = (l2 >= 0) & (l2 < LQ);
            const float* sa = Asrc + ((size_t)(bA[rr] << 9) + (v ? l2 : 0)) * DD + off;
            cp16(aAd0 + st * STB_A + rr * ROW32, sa, v);
        }
        cp16(bAd0 + st * STB_B,         wr0 + kk0, true);
        cp16(bAd0 + st * STB_B + ROW32, wr1 + kk0, true);
    };

    load_tile(0, 0);
    asm volatile("cp.async.commit_group;");
    load_tile(1, 1);
    asm volatile("cp.async.commit_group;");
    asm volatile("cp.async.wait_group 1;");
    __syncthreads();

    const int NIT = KDIM / 16;   // 72
    int st_next = 2, buf = 0;
    for (int it = 0; it < NIT; ++it) {
        if (it + 2 < NIT) load_tile(it + 2, st_next);
        asm volatile("cp.async.commit_group;");
        if (++st_next == STAGES) st_next = 0;

        const float* Ab = As + buf * 128 * ROWSTRIDE;
        const float* Bb = Bs + buf * 64 * ROWSTRIDE;
        #pragma unroll
        for (int ks = 0; ks < 2; ++ks) {
            const int pc = ks * 8 + 2 * tig;
            float2 bf[4];
            #pragma unroll
            for (int nt = 0; nt < 4; ++nt)
                bf[nt] = *(const float2*)&Bb[(n_base + nt * 8 + grp) * ROWSTRIDE + pc];
            #pragma unroll
            for (int mt = 0; mt < 4; ++mt) {
                const int ar = m_base + mt * 16 + grp;
                const float2 a02 = *(const float2*)&Ab[ar * ROWSTRIDE + pc];
                const float2 a13 = *(const float2*)&Ab[(ar + 8) * ROWSTRIDE + pc];
                const unsigned af[4] = {
                    __float_as_uint(a02.x), __float_as_uint(a13.x),
                    __float_as_uint(a02.y), __float_as_uint(a13.y) };
                #pragma unroll
                for (int nt = 0; nt < 4; ++nt) {
                    const unsigned bb[2] = { __float_as_uint(bf[nt].x),
                                             __float_as_uint(bf[nt].y) };
                    mma_tf32(acc[mt][nt], af, bb);
                }
            }
        }
        if (++buf == STAGES) buf = 0;

        asm volatile("cp.async.wait_group 1;");
        __syncthreads();
    }

    #pragma unroll
    for (int mt = 0; mt < 4; ++mt) {
        const int mrow = m0 + m_base + mt * 16 + grp;
        #pragma unroll
        for (int nt = 0; nt < 4; ++nt) {
            const int fc = f0 + n_base + nt * 8 + 2 * tig;
            const float b0v = bias[fc], b1v = bias[fc + 1];
            float2 r0 = make_float2(acc[mt][nt][0] + b0v, acc[mt][nt][1] + b1v);
            float2 r1 = make_float2(acc[mt][nt][2] + b0v, acc[mt][nt][3] + b1v);
            *(float2*)&Y[(size_t)mrow * FF + fc] = r0;
            *(float2*)&Y[(size_t)(mrow + 8) * FF + fc] = r1;
        }
    }
}

// ---------------------------------------------------------------------------
__device__ __forceinline__ float2 block_reduce2(float s, float q)
{
    __shared__ float sh[8];
    __syncthreads();
    const int lane = threadIdx.x & 31;
    const int w    = threadIdx.x >> 5;
    #pragma unroll
    for (int o = 16; o > 0; o >>= 1) {
        s += __shfl_down_sync(0xffffffffu, s, o);
        q += __shfl_down_sync(0xffffffffu, q, o);
    }
    if (lane == 0) { sh[w] = s; sh[4 + w] = q; }
    __syncthreads();
    if (threadIdx.x == 0) {
        sh[0] = sh[0] + sh[1] + sh[2] + sh[3];
        sh[4] = sh[4] + sh[5] + sh[6] + sh[7];
    }
    __syncthreads();
    return make_float2(sh[0], sh[4]);
}

__global__ __launch_bounds__(128) void ln_relu_kernel(
    const float* __restrict__ In, const float* __restrict__ gam,
    const float* __restrict__ bet, float* __restrict__ Out)
{
    const int row = blockIdx.x;
    const int t   = threadIdx.x;
    const float* p = In + (size_t)row * FF;
    float v0 = p[t], v1 = p[t + 128], v2 = p[t + 256];
    float2 r = block_reduce2(v0 + v1 + v2, v0 * v0 + v1 * v1 + v2 * v2);
    const float mu  = r.x * (1.0f / FF);
    const float var = r.y * (1.0f / FF) - mu * mu;
    const float rs  = rsqrtf(var + LN_EPS);
    float* o = Out + (size_t)row * FF;
    float v[3] = {v0, v1, v2};
    #pragma unroll
    for (int i = 0; i < 3; i++) {
        const int f = t + i * 128;
        const float h = fmaxf((v[i] - mu) * rs * gam[f] + bet[f], 0.0f);
        const int blk = f >> 4, j = f & 15;
        o[(blk << 4) + perm16(j)] = __uint_as_float(f2tf(h));
    }
}

__global__ __launch_bounds__(128) void ln_linear_kernel(
    const float* __restrict__ In, const float* __restrict__ gam,
    const float* __restrict__ bet, const float* __restrict__ lw,
    const float* __restrict__ lb, float* __restrict__ dur)
{
    const int row = blockIdx.x;
    const int t   = threadIdx.x;
    const float* p = In + (size_t)row * FF;
    float v0 = p[t], v1 = p[t + 128], v2 = p[t + 256];
    float2 r = block_reduce2(v0 + v1 + v2, v0 * v0 + v1 * v1 + v2 * v2);
    const float mu  = r.x * (1.0f / FF);
    const float var = r.y * (1.0f / FF) - mu * mu;
    const float rs  = rsqrtf(var + LN_EPS);
    float v[3] = {v0, v1, v2};
    float acc = 0.0f;
    #pragma unroll
    for (int i = 0; i < 3; i++) {
        const int f = t + i * 128;
        float h = fmaxf((v[i] - mu) * rs * gam[f] + bet[f], 0.0f);
        acc += h * lw[f];
    }
    float2 r2 = block_reduce2(acc, 0.0f);
    if (t == 0) dur[row] = fmaxf(r2.x + lb[0], 0.0f);
}

// ---------------------------------------------------------------------------
extern "C" void kernel_launch(void* const* d_in, const int* in_sizes, int n_in,
                              void* d_out, int out_size)
{
    const float* x     = (const float*)d_in[0];
    const float* c1_w  = (const float*)d_in[1];
    const float* c1_b  = (const float*)d_in[2];
    const float* ln1_g = (const float*)d_in[3];
    const float* ln1_b = (const float*)d_in[4];
    const float* c2_w  = (const float*)d_in[5];
    const float* c2_b  = (const float*)d_in[6];
    const float* ln2_g = (const float*)d_in[7];
    const float* ln2_b = (const float*)d_in[8];
    const float* lin_w = (const float*)d_in[9];
    const float* lin_b = (const float*)d_in[10];
    const int*   target= (const int*)d_in[11];

    const int M = (out_size - BB * LQ) / (BB * DD);

    float* buf1; cudaGetSymbolAddress((void**)&buf1, g_buf1);
    float* buf2; cudaGetSymbolAddress((void**)&buf2, g_buf2);
    float* xp;   cudaGetSymbolAddress((void**)&xp,   g_xp);
    float* w1r;  cudaGetSymbolAddress((void**)&w1r,  g_w1r);
    float* w2r;  cudaGetSymbolAddress((void**)&w2r,  g_w2r);

    float* out_expand = (float*)d_out;
    float* out_dur    = (float*)d_out + (size_t)BB * M * DD;

    const int smem_bytes = STAGES * (128 + 64) * ROWSTRIDE * 4;  // 55296
    cudaFuncSetAttribute(conv_expand_kernel,
                         cudaFuncAttributeMaxDynamicSharedMemorySize, smem_bytes);

    const int exp_total = BB * (M >> 3);       // 16384 frame-groups
    const int exp_half  = exp_total / 2;

    // Single stream: prep, then conv1+expandA, LN, conv2+expandB, LN+linear.
    prep_all_kernel<<<NPX + NWR + BB, 256>>>(x, xp, c1_w, w1r, c2_w, w2r, target);
    conv_expand_kernel<<<GEMM_BLOCKS + exp_half, 128, smem_bytes>>>(
        xp, w1r, c1_b, buf1, x, out_expand, M, 0);
    ln_relu_kernel<<<MROWS, 128>>>(buf1, ln1_g, ln1_b, buf2);
    conv_expand_kernel<<<GEMM_BLOCKS + (exp_total - exp_half), 128, smem_bytes>>>(
        buf2, w2r, c2_b, buf1, x, out_expand, M, exp_half);
    ln_linear_kernel<<<MROWS, 128>>>(buf1, ln2_g, ln2_b, lin_w, lin_b, out_dur);
}

// round 9
// speedup vs baseline: 1.3607x; 1.3445x over previous
#include <cuda_runtime.h>
#include <cuda_fp16.h>
#include <math.h>

#define BB   32
#define LQ   512
#define DD   384
#define FF   384
#define MROWS (BB*LQ)      // 16384
#define KDIM  (DD*3)       // 1152 (halves, k-major logical)
#define LN_EPS 1e-5f
#define STAGES 3
#define RSH 48             // smem row stride in halves (96 B = 24 words)
#define GEMM_BLOCKS ((MROWS/128)*(FF/64))   // 768
#define NPX (MROWS*DD/256)                  // 24576
#define NWR (FF*2)                          // 768

// Scratch (no allocations allowed).
__device__ float  g_buf1[(size_t)MROWS * FF];     // conv outputs (fp32)
__device__ __half g_buf2h[(size_t)MROWS * FF];    // ln_relu out (fp16, permuted)
__device__ __half g_xph [(size_t)MROWS * DD];     // x (fp16, permuted)
__device__ __half g_w1rh[(size_t)FF * KDIM];
__device__ __half g_w2rh[(size_t)FF * KDIM];
__device__ int    g_cum[BB * LQ];

// Half-pair permutation within each 16-half block: pair p=j>>1 goes to
// position (p<4 ? 2p : 2(p-4)+1), so pairs (tig, tig+4) are adjacent -> LDS.64.
__device__ __forceinline__ int perm16h(int j)
{
    const int p = j >> 1;
    const int pos = (p < 4) ? 2 * p : 2 * (p - 4) + 1;
    return pos * 2 + (j & 1);
}

// ---------------------------------------------------------------------------
// Fused prep: [0,NPX) x fp32->fp16 + permute ; [NPX,NPX+NWR) W reorder ;
// then BB cumsum scans.
// ---------------------------------------------------------------------------
__global__ __launch_bounds__(256) void prep_all_kernel(
    const float* __restrict__ x, __half* __restrict__ xp,
    const float* __restrict__ W1, __half* __restrict__ Wr1,
    const float* __restrict__ W2, __half* __restrict__ Wr2,
    const int* __restrict__ target)
{
    const int bidx = blockIdx.x;
    const int t = threadIdx.x;

    if (bidx < NPX) {
        const int idx = bidx * 256 + t;
        const int row = idx / DD;
        const int col = idx - row * DD;
        const int blk = col >> 4, j = col & 15;
        xp[(size_t)row * DD + (blk << 4) + perm16h(j)] = __float2half_rn(x[idx]);
    } else if (bidx < NPX + NWR) {
        const int r2 = bidx - NPX;
        const float* W  = (r2 >= FF) ? W2 : W1;
        __half*     Wr = (r2 >= FF) ? Wr2 : Wr1;
        const int f = (r2 >= FF) ? r2 - FF : r2;
        for (int i = t; i < KDIM; i += 256) {
            const int kseg = i / DD;
            const int r    = i - kseg * DD;
            const int blk  = r >> 4, j = r & 15;
            const int dst  = kseg * DD + (blk << 4) + perm16h(j);
            Wr[(size_t)f * KDIM + dst] =
                __float2half_rn(W[(size_t)f * KDIM + (blk * 16 + j) * 3 + kseg]);
        }
    } else {
        __shared__ int s[512];
        const int b = bidx - (NPX + NWR);
        s[t]       = target[b * LQ + t];
        s[t + 256] = target[b * LQ + t + 256];
        __syncthreads();
        for (int off = 1; off < 512; off <<= 1) {
            const int v0 = (t >= off) ? s[t - off] : 0;
            const int v1 = s[t + 256 - off];
            __syncthreads();
            s[t] += v0;
            s[t + 256] += v1;
            __syncthreads();
        }
        g_cum[b * LQ + t]       = s[t];
        g_cum[b * LQ + t + 256] = s[t + 256];
    }
}

__device__ __forceinline__ void mma_f16(float c[4], unsigned a0, unsigned a1,
                                        unsigned a2, unsigned a3,
                                        unsigned b0, unsigned b1)
{
    asm volatile(
        "mma.sync.aligned.m16n8k16.row.col.f32.f16.f16.f32 "
        "{%0,%1,%2,%3}, {%4,%5,%6,%7}, {%8,%9}, {%0,%1,%2,%3};"
        : "+f"(c[0]), "+f"(c[1]), "+f"(c[2]), "+f"(c[3])
        : "r"(a0), "r"(a1), "r"(a2), "r"(a3), "r"(b0), "r"(b1));
}

__device__ __forceinline__ void cp16(unsigned dst, const void* src, bool p)
{
    const int sz = p ? 16 : 0;
    asm volatile("cp.async.cg.shared.global [%0], [%1], 16, %2;\n"
                 :: "r"(dst), "l"(src), "r"(sz));
}

// ---------------------------------------------------------------------------
// Conv-as-GEMM on fp16 mma m16n8k16 (fp32 accum). CTA 128x64, BK=32 halves,
// 128 threads, warps 2m x 2n... (warp tile 64x32), 3-stage cp.async.
// Blocks >= GEMM_BLOCKS do expand frame-groups.
// ---------------------------------------------------------------------------
__global__ __launch_bounds__(128, 4) void conv_expand_kernel(
    const __half* __restrict__ Asrc, const __half* __restrict__ Wr,
    const float* __restrict__ bias, float* __restrict__ Y,
    const float* __restrict__ X, float* __restrict__ out,
    int M, int exp_base)
{
    if (blockIdx.x >= GEMM_BLOCKS) {
        // ---------------- expand ----------------
        if (threadIdx.x < 96) {
            const int g   = blockIdx.x - GEMM_BLOCKS + exp_base;
            const int gpb = M >> 3;
            const int b   = g / gpb;
            const int fg  = g - b * gpb;
            const int* cum = g_cum + b * LQ;
            const int total = __ldg(&cum[LQ - 1]);
            #pragma unroll
            for (int i = 0; i < 8; ++i) {
                const int tfr = fg * 8 + i;
                float4* dst = (float4*)(out + ((size_t)b * M + tfr) * DD);
                if (tfr >= total) {
                    __stcs(&dst[threadIdx.x], make_float4(0.f, 0.f, 0.f, 0.f));
                } else {
                    int lo = 0, hi = LQ;
                    while (lo < hi) {
                        const int mid = (lo + hi) >> 1;
                        if (__ldg(&cum[mid]) <= tfr) lo = mid + 1; else hi = mid;
                    }
                    const int idx = min(lo, LQ - 1);
                    const float4* src = (const float4*)(X + ((size_t)b * LQ + idx) * DD);
                    __stcs(&dst[threadIdx.x], __ldg(&src[threadIdx.x]));
                }
            }
        }
        return;
    }

    // ---------------- conv ----------------
    extern __shared__ __half smh[];
    __half* As = smh;                          // [STAGES][128][RSH]
    __half* Bs = smh + STAGES * 128 * RSH;     // [STAGES][64][RSH]

    const int m0 = (blockIdx.x & 127) * 128;
    const int f0 = (blockIdx.x >> 7) * 64;
    const int t  = threadIdx.x;
    const int lane = t & 31, grp = lane >> 2, tig = lane & 3;
    const int warp = t >> 5;
    const int m_base = (warp & 1) * 64;
    const int n_base = (warp >> 1) * 32;

    const int lrow = t >> 2;            // 0..31
    const int c    = t & 3;             // 16B chunk (8 halves) within 64B row

    int bA[4], lA[4];
    #pragma unroll
    for (int rr = 0; rr < 4; ++rr) {
        const int m = m0 + lrow + rr * 32;
        bA[rr] = m >> 9;
        lA[rr] = m & 511;
    }

    const unsigned aAd0 = (unsigned)__cvta_generic_to_shared(&As[lrow * RSH + c * 8]);
    const unsigned bAd0 = (unsigned)__cvta_generic_to_shared(&Bs[lrow * RSH + c * 8]);
    const unsigned STB_A = 128 * RSH * 2;   // bytes per A stage (12288)
    const unsigned STB_B = 64 * RSH * 2;    // 6144
    const unsigned ROW32 = 32 * RSH * 2;    // 3072

    const __half* wr0 = Wr + (size_t)(f0 + lrow) * KDIM + c * 8;
    const __half* wr1 = Wr + (size_t)(f0 + lrow + 32) * KDIM + c * 8;

    float acc[4][4][4] = {};

    auto load_tile = [&](int it, int st) {
        const int kk0  = it * 32;                      // half index, k-major
        const int kseg = (kk0 >= 384) + (kk0 >= 768);  // BK=32 divides 384
        const int off  = kk0 - kseg * DD + c * 8;
        #pragma unroll
        for (int rr = 0; rr < 4; ++rr) {
            const int l2 = lA[rr] + kseg - 1;
            const bool v = (l2 >= 0) & (l2 < LQ);
            const __half* sa = Asrc + ((size_t)(bA[rr] << 9) + (v ? l2 : 0)) * DD + off;
            cp16(aAd0 + st * STB_A + rr * ROW32, sa, v);
        }
        cp16(bAd0 + st * STB_B,         wr0 + kk0, true);
        cp16(bAd0 + st * STB_B + ROW32, wr1 + kk0, true);
    };

    load_tile(0, 0);
    asm volatile("cp.async.commit_group;");
    load_tile(1, 1);
    asm volatile("cp.async.commit_group;");
    asm volatile("cp.async.wait_group 1;");
    __syncthreads();

    const int NIT = KDIM / 32;   // 36
    int st_next = 2, buf = 0;
    for (int it = 0; it < NIT; ++it) {
        if (it + 2 < NIT) load_tile(it + 2, st_next);
        asm volatile("cp.async.commit_group;");
        if (++st_next == STAGES) st_next = 0;

        const __half* Ab = As + buf * 128 * RSH;
        const __half* Bb = Bs + buf * 64 * RSH;
        #pragma unroll
        for (int ks = 0; ks < 2; ++ks) {
            const int pch = ks * 16 + tig * 4;   // half offset of (k2t,k2t+1,k2t+8,k2t+9)
            uint2 bf[4];
            #pragma unroll
            for (int nt = 0; nt < 4; ++nt)
                bf[nt] = *(const uint2*)&Bb[(n_base + nt * 8 + grp) * RSH + pch];
            #pragma unroll
            for (int mt = 0; mt < 4; ++mt) {
                const int ar = m_base + mt * 16 + grp;
                const uint2 ua = *(const uint2*)&Ab[ar * RSH + pch];        // a0|a2
                const uint2 ub = *(const uint2*)&Ab[(ar + 8) * RSH + pch];  // a1|a3
                #pragma unroll
                for (int nt = 0; nt < 4; ++nt)
                    mma_f16(acc[mt][nt], ua.x, ub.x, ua.y, ub.y,
                            bf[nt].x, bf[nt].y);
            }
        }
        if (++buf == STAGES) buf = 0;

        asm volatile("cp.async.wait_group 1;");
        __syncthreads();
    }

    #pragma unroll
    for (int mt = 0; mt < 4; ++mt) {
        const int mrow = m0 + m_base + mt * 16 + grp;
        #pragma unroll
        for (int nt = 0; nt < 4; ++nt) {
            const int fc = f0 + n_base + nt * 8 + 2 * tig;
            const float b0v = bias[fc], b1v = bias[fc + 1];
            float2 r0 = make_float2(acc[mt][nt][0] + b0v, acc[mt][nt][1] + b1v);
            float2 r1 = make_float2(acc[mt][nt][2] + b0v, acc[mt][nt][3] + b1v);
            *(float2*)&Y[(size_t)mrow * FF + fc] = r0;
            *(float2*)&Y[(size_t)(mrow + 8) * FF + fc] = r1;
        }
    }
}

// ---------------------------------------------------------------------------
__device__ __forceinline__ float2 block_reduce2(float s, float q)
{
    __shared__ float sh[8];
    __syncthreads();
    const int lane = threadIdx.x & 31;
    const int w    = threadIdx.x >> 5;
    #pragma unroll
    for (int o = 16; o > 0; o >>= 1) {
        s += __shfl_down_sync(0xffffffffu, s, o);
        q += __shfl_down_sync(0xffffffffu, q, o);
    }
    if (lane == 0) { sh[w] = s; sh[4 + w] = q; }
    __syncthreads();
    if (threadIdx.x == 0) {
        sh[0] = sh[0] + sh[1] + sh[2] + sh[3];
        sh[4] = sh[4] + sh[5] + sh[6] + sh[7];
    }
    __syncthreads();
    return make_float2(sh[0], sh[4]);
}

// LN+ReLU -> fp16 permuted output (feeds conv2 A path).
__global__ __launch_bounds__(128) void ln_relu_kernel(
    const float* __restrict__ In, const float* __restrict__ gam,
    const float* __restrict__ bet, __half* __restrict__ Out)
{
    const int row = blockIdx.x;
    const int t   = threadIdx.x;
    const float* p = In + (size_t)row * FF;
    float v0 = p[t], v1 = p[t + 128], v2 = p[t + 256];
    float2 r = block_reduce2(v0 + v1 + v2, v0 * v0 + v1 * v1 + v2 * v2);
    const float mu  = r.x * (1.0f / FF);
    const float var = r.y * (1.0f / FF) - mu * mu;
    const float rs  = rsqrtf(var + LN_EPS);
    __half* o = Out + (size_t)row * FF;
    float v[3] = {v0, v1, v2};
    #pragma unroll
    for (int i = 0; i < 3; i++) {
        const int f = t + i * 128;
        const float h = fmaxf((v[i] - mu) * rs * gam[f] + bet[f], 0.0f);
        const int blk = f >> 4, j = f & 15;
        o[(blk << 4) + perm16h(j)] = __float2half_rn(h);
    }
}

__global__ __launch_bounds__(128) void ln_linear_kernel(
    const float* __restrict__ In, const float* __restrict__ gam,
    const float* __restrict__ bet, const float* __restrict__ lw,
    const float* __restrict__ lb, float* __restrict__ dur)
{
    const int row = blockIdx.x;
    const int t   = threadIdx.x;
    const float* p = In + (size_t)row * FF;
    float v0 = p[t], v1 = p[t + 128], v2 = p[t + 256];
    float2 r = block_reduce2(v0 + v1 + v2, v0 * v0 + v1 * v1 + v2 * v2);
    const float mu  = r.x * (1.0f / FF);
    const float var = r.y * (1.0f / FF) - mu * mu;
    const float rs  = rsqrtf(var + LN_EPS);
    float v[3] = {v0, v1, v2};
    float acc = 0.0f;
    #pragma unroll
    for (int i = 0; i < 3; i++) {
        const int f = t + i * 128;
        float h = fmaxf((v[i] - mu) * rs * gam[f] + bet[f], 0.0f);
        acc += h * lw[f];
    }
    float2 r2 = block_reduce2(acc, 0.0f);
    if (t == 0) dur[row] = fmaxf(r2.x + lb[0], 0.0f);
}

// ---------------------------------------------------------------------------
extern "C" void kernel_launch(void* const* d_in, const int* in_sizes, int n_in,
                              void* d_out, int out_size)
{
    const float* x     = (const float*)d_in[0];
    const float* c1_w  = (const float*)d_in[1];
    const float* c1_b  = (const float*)d_in[2];
    const float* ln1_g = (const float*)d_in[3];
    const float* ln1_b = (const float*)d_in[4];
    const float* c2_w  = (const float*)d_in[5];
    const float* c2_b  = (const float*)d_in[6];
    const float* ln2_g = (const float*)d_in[7];
    const float* ln2_b = (const float*)d_in[8];
    const float* lin_w = (const float*)d_in[9];
    const float* lin_b = (const float*)d_in[10];
    const int*   target= (const int*)d_in[11];

    const int M = (out_size - BB * LQ) / (BB * DD);

    float*  buf1;  cudaGetSymbolAddress((void**)&buf1,  g_buf1);
    __half* buf2h; cudaGetSymbolAddress((void**)&buf2h, g_buf2h);
    __half* xph;   cudaGetSymbolAddress((void**)&xph,   g_xph);
    __half* w1rh;  cudaGetSymbolAddress((void**)&w1rh,  g_w1rh);
    __half* w2rh;  cudaGetSymbolAddress((void**)&w2rh,  g_w2rh);

    float* out_expand = (float*)d_out;
    float* out_dur    = (float*)d_out + (size_t)BB * M * DD;

    const int smem_bytes = STAGES * (128 + 64) * RSH * 2;  // 55296
    cudaFuncSetAttribute(conv_expand_kernel,
                         cudaFuncAttributeMaxDynamicSharedMemorySize, smem_bytes);

    const int exp_total = BB * (M >> 3);
    const int exp_half  = exp_total / 2;

    prep_all_kernel<<<NPX + NWR + BB, 256>>>(x, xph, c1_w, w1rh, c2_w, w2rh, target);
    conv_expand_kernel<<<GEMM_BLOCKS + exp_half, 128, smem_bytes>>>(
        xph, w1rh, c1_b, buf1, x, out_expand, M, 0);
    ln_relu_kernel<<<MROWS, 128>>>(buf1, ln1_g, ln1_b, buf2h);
    conv_expand_kernel<<<GEMM_BLOCKS + (exp_total - exp_half), 128, smem_bytes>>>(
        buf2h, w2rh, c2_b, buf1, x, out_expand, M, exp_half);
    ln_linear_kernel<<<MROWS, 128>>>(buf1, ln2_g, ln2_b, lin_w, lin_b, out_dur);
}

// round 10
// speedup vs baseline: 1.5092x; 1.1091x over previous
#include <cuda_runtime.h>
#include <cuda_fp16.h>
#include <math.h>

#define BB   32
#define LQ   512
#define DD   384
#define FF   384
#define MROWS (BB*LQ)      // 16384
#define KDIM  (DD*3)       // 1152 halves
#define LN_EPS 1e-5f
#define STAGES 3
#define RSH 48             // smem row stride in halves (96 B)
#define GEMM_BLOCKS ((MROWS/64)*(FF/64))    // 1536
#define NPX2 (MROWS*DD/2/256)               // 12288
#define NWR (FF*2)                          // 768

// Scratch (no allocations allowed).
__device__ float  g_buf1[(size_t)MROWS * FF];
__device__ __half g_buf2h[(size_t)MROWS * FF];
__device__ __half g_xph [(size_t)MROWS * DD];
__device__ __half g_w1rh[(size_t)FF * KDIM];
__device__ __half g_w2rh[(size_t)FF * KDIM];
__device__ int    g_cum[BB * LQ];

// Half-pair permutation within each 16-half block: pair p -> position
// (p<4 ? 2p : 2(p-4)+1); halves within a pair stay adjacent.
__device__ __forceinline__ int perm16h(int j)
{
    const int p = j >> 1;
    const int pos = (p < 4) ? 2 * p : 2 * (p - 4) + 1;
    return pos * 2 + (j & 1);
}

// ---------------------------------------------------------------------------
// Fused prep: [0,NPX2) x fp32->fp16 pairwise ; [NPX2,NPX2+NWR) W reorder ;
// then BB cumsum scans.
// ---------------------------------------------------------------------------
__global__ __launch_bounds__(256) void prep_all_kernel(
    const float* __restrict__ x, __half* __restrict__ xp,
    const float* __restrict__ W1, __half* __restrict__ Wr1,
    const float* __restrict__ W2, __half* __restrict__ Wr2,
    const int* __restrict__ target)
{
    const int bidx = blockIdx.x;
    const int t = threadIdx.x;

    if (bidx < NPX2) {
        const int idx2 = bidx * 256 + t;          // pair index
        const int row  = idx2 / 192;              // DD/2 pairs per row
        const int pc   = idx2 - row * 192;
        const int blk  = pc >> 3, p = pc & 7;
        const int pos  = (p < 4) ? 2 * p : 2 * (p - 4) + 1;
        const float2 v = *(const float2*)&x[(size_t)row * DD + (blk << 4) + p * 2];
        *(__half2*)&xp[(size_t)row * DD + (blk << 4) + pos * 2] =
            __floats2half2_rn(v.x, v.y);
    } else if (bidx < NPX2 + NWR) {
        const int r2 = bidx - NPX2;
        const float* W  = (r2 >= FF) ? W2 : W1;
        __half*     Wr = (r2 >= FF) ? Wr2 : Wr1;
        const int f = (r2 >= FF) ? r2 - FF : r2;
        for (int i = t; i < KDIM; i += 256) {
            const int kseg = i / DD;
            const int r    = i - kseg * DD;
            const int blk  = r >> 4, j = r & 15;
            const int dst  = kseg * DD + (blk << 4) + perm16h(j);
            Wr[(size_t)f * KDIM + dst] =
                __float2half_rn(W[(size_t)f * KDIM + (blk * 16 + j) * 3 + kseg]);
        }
    } else {
        __shared__ int s[512];
        const int b = bidx - (NPX2 + NWR);
        s[t]       = target[b * LQ + t];
        s[t + 256] = target[b * LQ + t + 256];
        __syncthreads();
        for (int off = 1; off < 512; off <<= 1) {
            const int v0 = (t >= off) ? s[t - off] : 0;
            const int v1 = s[t + 256 - off];
            __syncthreads();
            s[t] += v0;
            s[t + 256] += v1;
            __syncthreads();
        }
        g_cum[b * LQ + t]       = s[t];
        g_cum[b * LQ + t + 256] = s[t + 256];
    }
}

__device__ __forceinline__ void mma_f16(float c[4], unsigned a0, unsigned a1,
                                        unsigned a2, unsigned a3,
                                        unsigned b0, unsigned b1)
{
    asm volatile(
        "mma.sync.aligned.m16n8k16.row.col.f32.f16.f16.f32 "
        "{%0,%1,%2,%3}, {%4,%5,%6,%7}, {%8,%9}, {%0,%1,%2,%3};"
        : "+f"(c[0]), "+f"(c[1]), "+f"(c[2]), "+f"(c[3])
        : "r"(a0), "r"(a1), "r"(a2), "r"(a3), "r"(b0), "r"(b1));
}

__device__ __forceinline__ void cp16(unsigned dst, const void* src, bool p)
{
    const int sz = p ? 16 : 0;
    asm volatile("cp.async.cg.shared.global [%0], [%1], 16, %2;\n"
                 :: "r"(dst), "l"(src), "r"(sz));
}

// ---------------------------------------------------------------------------
// Conv fp16 mma: CTA tile 64x64, BK=32, 128 threads, 4 warps 2x2 (warp 32x32),
// 3-stage cp.async, 5 CTAs/SM. Blocks >= GEMM_BLOCKS: expand (all 128 lanes).
// ---------------------------------------------------------------------------
__global__ __launch_bounds__(128, 5) void conv_expand_kernel(
    const __half* __restrict__ Asrc, const __half* __restrict__ Wr,
    const float* __restrict__ bias, float* __restrict__ Y,
    const float* __restrict__ X, float* __restrict__ out,
    int M, int exp_base)
{
    if (blockIdx.x >= GEMM_BLOCKS) {
        // ---------------- expand: 8 frames = 768 float4, flat over 128 thr ----
        const int g   = blockIdx.x - GEMM_BLOCKS + exp_base;
        const int gpb = M >> 3;
        const int b   = g / gpb;
        const int fg  = g - b * gpb;
        const int* cum = g_cum + b * LQ;
        const int total = __ldg(&cum[LQ - 1]);
        float4* obase = (float4*)(out + (size_t)b * M * DD) + (size_t)fg * 768;
        #pragma unroll
        for (int i = 0; i < 6; ++i) {
            const int idx  = i * 128 + threadIdx.x;    // 0..767
            const int fr   = fg * 8 + idx / 96;
            const int lane = idx - (idx / 96) * 96;
            if (fr >= total) {
                __stcs(&obase[idx], make_float4(0.f, 0.f, 0.f, 0.f));
            } else {
                int lo = 0, hi = LQ;
                while (lo < hi) {
                    const int mid = (lo + hi) >> 1;
                    if (__ldg(&cum[mid]) <= fr) lo = mid + 1; else hi = mid;
                }
                const int sidx = min(lo, LQ - 1);
                const float4* src = (const float4*)(X + ((size_t)b * LQ + sidx) * DD);
                __stcs(&obase[idx], __ldg(&src[lane]));
            }
        }
        return;
    }

    // ---------------- conv ----------------
    extern __shared__ __half smh[];
    __half* As = smh;                          // [STAGES][64][RSH]
    __half* Bs = smh + STAGES * 64 * RSH;      // [STAGES][64][RSH]

    const int m0 = (blockIdx.x & 255) * 64;
    const int f0 = (blockIdx.x >> 8) * 64;
    const int t  = threadIdx.x;
    const int lane = t & 31, grp = lane >> 2, tig = lane & 3;
    const int warp = t >> 5;
    const int m_base = (warp & 1) * 32;
    const int n_base = (warp >> 1) * 32;

    const int lrow = t >> 2;            // 0..31
    const int c    = t & 3;             // 16B chunk within 64B of data

    int bA[2], lA[2];
    #pragma unroll
    for (int rr = 0; rr < 2; ++rr) {
        const int m = m0 + lrow + rr * 32;
        bA[rr] = m >> 9;
        lA[rr] = m & 511;
    }

    const unsigned aAd0 = (unsigned)__cvta_generic_to_shared(&As[lrow * RSH + c * 8]);
    const unsigned bAd0 = (unsigned)__cvta_generic_to_shared(&Bs[lrow * RSH + c * 8]);
    const unsigned STB   = 64 * RSH * 2;    // 6144 B per stage (A or B)
    const unsigned ROW32 = 32 * RSH * 2;    // 3072

    const __half* wr0 = Wr + (size_t)(f0 + lrow) * KDIM + c * 8;
    const __half* wr1 = Wr + (size_t)(f0 + lrow + 32) * KDIM + c * 8;

    float acc[2][4][4] = {};

    auto load_tile = [&](int it, int st) {
        const int kk0  = it * 32;
        const int kseg = (kk0 >= 384) + (kk0 >= 768);
        const int off  = kk0 - kseg * DD + c * 8;
        #pragma unroll
        for (int rr = 0; rr < 2; ++rr) {
            const int l2 = lA[rr] + kseg - 1;
            const bool v = (l2 >= 0) & (l2 < LQ);
            const __half* sa = Asrc + ((size_t)(bA[rr] << 9) + (v ? l2 : 0)) * DD + off;
            cp16(aAd0 + st * STB + rr * ROW32, sa, v);
        }
        cp16(bAd0 + st * STB,         wr0 + kk0, true);
        cp16(bAd0 + st * STB + ROW32, wr1 + kk0, true);
    };

    load_tile(0, 0);
    asm volatile("cp.async.commit_group;");
    load_tile(1, 1);
    asm volatile("cp.async.commit_group;");
    asm volatile("cp.async.wait_group 1;");
    __syncthreads();

    const int NIT = KDIM / 32;   // 36
    int st_next = 2, buf = 0;
    for (int it = 0; it < NIT; ++it) {
        if (it + 2 < NIT) load_tile(it + 2, st_next);
        asm volatile("cp.async.commit_group;");
        if (++st_next == STAGES) st_next = 0;

        const __half* Ab = As + buf * 64 * RSH;
        const __half* Bb = Bs + buf * 64 * RSH;
        #pragma unroll
        for (int ks = 0; ks < 2; ++ks) {
            const int pch = ks * 16 + tig * 4;
            uint2 bf[4];
            #pragma unroll
            for (int nt = 0; nt < 4; ++nt)
                bf[nt] = *(const uint2*)&Bb[(n_base + nt * 8 + grp) * RSH + pch];
            #pragma unroll
            for (int mt = 0; mt < 2; ++mt) {
                const int ar = m_base + mt * 16 + grp;
                const uint2 ua = *(const uint2*)&Ab[ar * RSH + pch];
                const uint2 ub = *(const uint2*)&Ab[(ar + 8) * RSH + pch];
                #pragma unroll
                for (int nt = 0; nt < 4; ++nt)
                    mma_f16(acc[mt][nt], ua.x, ub.x, ua.y, ub.y,
                            bf[nt].x, bf[nt].y);
            }
        }
        if (++buf == STAGES) buf = 0;

        asm volatile("cp.async.wait_group 1;");
        __syncthreads();
    }

    #pragma unroll
    for (int mt = 0; mt < 2; ++mt) {
        const int mrow = m0 + m_base + mt * 16 + grp;
        #pragma unroll
        for (int nt = 0; nt < 4; ++nt) {
            const int fc = f0 + n_base + nt * 8 + 2 * tig;
            const float b0v = bias[fc], b1v = bias[fc + 1];
            float2 r0 = make_float2(acc[mt][nt][0] + b0v, acc[mt][nt][1] + b1v);
            float2 r1 = make_float2(acc[mt][nt][2] + b0v, acc[mt][nt][3] + b1v);
            *(float2*)&Y[(size_t)mrow * FF + fc] = r0;
            *(float2*)&Y[(size_t)(mrow + 8) * FF + fc] = r1;
        }
    }
}

// ---------------------------------------------------------------------------
// (sum, sumsq) reduction over 128 threads of one row; sh8 = 8 floats per row.
__device__ __forceinline__ float2 row_reduce2(float s, float q, float* sh8)
{
    __syncthreads();
    const int lane = threadIdx.x & 31;
    const int w    = threadIdx.x >> 5;
    #pragma unroll
    for (int o = 16; o > 0; o >>= 1) {
        s += __shfl_down_sync(0xffffffffu, s, o);
        q += __shfl_down_sync(0xffffffffu, q, o);
    }
    if (lane == 0) { sh8[w] = s; sh8[4 + w] = q; }
    __syncthreads();
    if (threadIdx.x == 0) {
        sh8[0] = sh8[0] + sh8[1] + sh8[2] + sh8[3];
        sh8[4] = sh8[4] + sh8[5] + sh8[6] + sh8[7];
    }
    __syncthreads();
    return make_float2(sh8[0], sh8[4]);
}

// LN+ReLU -> fp16 permuted; 4 rows per block (threadIdx.y), 128 thr per row.
__global__ __launch_bounds__(512) void ln_relu_kernel(
    const float* __restrict__ In, const float* __restrict__ gam,
    const float* __restrict__ bet, __half* __restrict__ Out)
{
    __shared__ float sh[4][8];
    const int row = blockIdx.x * 4 + threadIdx.y;
    const int t   = threadIdx.x;
    const float* p = In + (size_t)row * FF;
    float v0 = p[t], v1 = p[t + 128], v2 = p[t + 256];
    float2 r = row_reduce2(v0 + v1 + v2, v0 * v0 + v1 * v1 + v2 * v2,
                           sh[threadIdx.y]);
    const float mu  = r.x * (1.0f / FF);
    const float var = r.y * (1.0f / FF) - mu * mu;
    const float rs  = rsqrtf(var + LN_EPS);
    __half* o = Out + (size_t)row * FF;
    float v[3] = {v0, v1, v2};
    #pragma unroll
    for (int i = 0; i < 3; i++) {
        const int f = t + i * 128;
        const float h = fmaxf((v[i] - mu) * rs * gam[f] + bet[f], 0.0f);
        const int blk = f >> 4, j = f & 15;
        o[(blk << 4) + perm16h(j)] = __float2half_rn(h);
    }
}

__global__ __launch_bounds__(512) void ln_linear_kernel(
    const float* __restrict__ In, const float* __restrict__ gam,
    const float* __restrict__ bet, const float* __restrict__ lw,
    const float* __restrict__ lb, float* __restrict__ dur)
{
    __shared__ float sh[4][8];
    const int row = blockIdx.x * 4 + threadIdx.y;
    const int t   = threadIdx.x;
    const float* p = In + (size_t)row * FF;
    float v0 = p[t], v1 = p[t + 128], v2 = p[t + 256];
    float2 r = row_reduce2(v0 + v1 + v2, v0 * v0 + v1 * v1 + v2 * v2,
                           sh[threadIdx.y]);
    const float mu  = r.x * (1.0f / FF);
    const float var = r.y * (1.0f / FF) - mu * mu;
    const float rs  = rsqrtf(var + LN_EPS);
    float v[3] = {v0, v1, v2};
    float acc = 0.0f;
    #pragma unroll
    for (int i = 0; i < 3; i++) {
        const int f = t + i * 128;
        float h = fmaxf((v[i] - mu) * rs * gam[f] + bet[f], 0.0f);
        acc += h * lw[f];
    }
    float2 r2 = row_reduce2(acc, 0.0f, sh[threadIdx.y]);
    if (t == 0) dur[row] = fmaxf(r2.x + lb[0], 0.0f);
}

// ---------------------------------------------------------------------------
extern "C" void kernel_launch(void* const* d_in, const int* in_sizes, int n_in,
                              void* d_out, int out_size)
{
    const float* x     = (const float*)d_in[0];
    const float* c1_w  = (const float*)d_in[1];
    const float* c1_b  = (const float*)d_in[2];
    const float* ln1_g = (const float*)d_in[3];
    const float* ln1_b = (const float*)d_in[4];
    const float* c2_w  = (const float*)d_in[5];
    const float* c2_b  = (const float*)d_in[6];
    const float* ln2_g = (const float*)d_in[7];
    const float* ln2_b = (const float*)d_in[8];
    const float* lin_w = (const float*)d_in[9];
    const float* lin_b = (const float*)d_in[10];
    const int*   target= (const int*)d_in[11];

    const int M = (out_size - BB * LQ) / (BB * DD);

    float*  buf1;  cudaGetSymbolAddress((void**)&buf1,  g_buf1);
    __half* buf2h; cudaGetSymbolAddress((void**)&buf2h, g_buf2h);
    __half* xph;   cudaGetSymbolAddress((void**)&xph,   g_xph);
    __half* w1rh;  cudaGetSymbolAddress((void**)&w1rh,  g_w1rh);
    __half* w2rh;  cudaGetSymbolAddress((void**)&w2rh,  g_w2rh);

    float* out_expand = (float*)d_out;
    float* out_dur    = (float*)d_out + (size_t)BB * M * DD;

    const int smem_bytes = STAGES * (64 + 64) * RSH * 2;  // 36864
    cudaFuncSetAttribute(conv_expand_kernel,
                         cudaFuncAttributeMaxDynamicSharedMemorySize, smem_bytes);

    const int exp_total = BB * (M >> 3);   // 16384
    const int exp_half  = exp_total / 2;

    prep_all_kernel<<<NPX2 + NWR + BB, 256>>>(x, xph, c1_w, w1rh, c2_w, w2rh, target);
    conv_expand_kernel<<<GEMM_BLOCKS + exp_half, 128, smem_bytes>>>(
        xph, w1rh, c1_b, buf1, x, out_expand, M, 0);
    ln_relu_kernel<<<MROWS / 4, dim3(128, 4)>>>(buf1, ln1_g, ln1_b, buf2h);
    conv_expand_kernel<<<GEMM_BLOCKS + (exp_total - exp_half), 128, smem_bytes>>>(
        buf2h, w2rh, c2_b, buf1, x, out_expand, M, exp_half);
    ln_linear_kernel<<<MROWS / 4, dim3(128, 4)>>>(buf1, ln2_g, ln2_b, lin_w, lin_b, out_dur);
}

// round 12
// speedup vs baseline: 1.8303x; 1.2128x over previous
#include <cuda_runtime.h>
#include <cuda_fp16.h>
#include <math.h>

#define BB   32
#define LQ   512
#define DD   384
#define FF   384
#define MROWS (BB*LQ)      // 16384
#define KDIM  (DD*3)       // 1152 halves
#define LN_EPS 1e-5f
#define STAGES 3
#define RSH 48             // smem row stride in halves (96 B)
#define GEMM_BLOCKS ((MROWS/64)*(FF/64))    // 1536
#define NPX2 (MROWS*DD/2/256)               // 12288
#define NWR (FF*2)                          // 768

// Scratch (no allocations allowed).
__device__ float  g_buf1[(size_t)MROWS * FF];
__device__ __half g_buf2h[(size_t)MROWS * FF];
__device__ __half g_xph [(size_t)MROWS * DD];
__device__ __half g_w1rh[(size_t)FF * KDIM];
__device__ __half g_w2rh[(size_t)FF * KDIM];
__device__ int    g_fidx[BB * 8192];        // frame -> source phoneme (-1 = pad)

// Half-pair permutation within each 16-half block: pair p -> position
// (p<4 ? 2p : 2(p-4)+1); halves within a pair stay adjacent.
__device__ __forceinline__ int perm16h(int j)
{
    const int p = j >> 1;
    const int pos = (p < 4) ? 2 * p : 2 * (p - 4) + 1;
    return pos * 2 + (j & 1);
}

// ---------------------------------------------------------------------------
// Fused prep: [0,NPX2) x fp32->fp16 pairwise ; [NPX2,NPX2+NWR) W reorder ;
// then BB*(M/256) frame-index blocks (each re-derives its batch's cumsum).
// ---------------------------------------------------------------------------
__global__ __launch_bounds__(256) void prep_all_kernel(
    const float* __restrict__ x, __half* __restrict__ xp,
    const float* __restrict__ W1, __half* __restrict__ Wr1,
    const float* __restrict__ W2, __half* __restrict__ Wr2,
    const int* __restrict__ target, int M)
{
    const int bidx = blockIdx.x;
    const int t = threadIdx.x;

    if (bidx < NPX2) {
        const int idx2 = bidx * 256 + t;          // pair index
        const int row  = idx2 / 192;              // DD/2 pairs per row
        const int pc   = idx2 - row * 192;
        const int blk  = pc >> 3, p = pc & 7;
        const int pos  = (p < 4) ? 2 * p : 2 * (p - 4) + 1;
        const float2 v = *(const float2*)&x[(size_t)row * DD + (blk << 4) + p * 2];
        *(__half2*)&xp[(size_t)row * DD + (blk << 4) + pos * 2] =
            __floats2half2_rn(v.x, v.y);
    } else if (bidx < NPX2 + NWR) {
        const int r2 = bidx - NPX2;
        const float* W  = (r2 >= FF) ? W2 : W1;
        __half*     Wr = (r2 >= FF) ? Wr2 : Wr1;
        const int f = (r2 >= FF) ? r2 - FF : r2;
        for (int i = t; i < KDIM; i += 256) {
            const int kseg = i / DD;
            const int r    = i - kseg * DD;
            const int blk  = r >> 4, j = r & 15;
            const int dst  = kseg * DD + (blk << 4) + perm16h(j);
            Wr[(size_t)f * KDIM + dst] =
                __float2half_rn(W[(size_t)f * KDIM + (blk * 16 + j) * 3 + kseg]);
        }
    } else {
        // frame-index block: 256 frames of one batch
        __shared__ int s[512];
        const int fb  = bidx - (NPX2 + NWR);
        const int bpB = M >> 8;                   // blocks per batch
        const int b   = fb / bpB;
        const int fr0 = (fb - b * bpB) * 256;
        s[t]       = target[b * LQ + t];
        s[t + 256] = target[b * LQ + t + 256];
        __syncthreads();
        for (int off = 1; off < 512; off <<= 1) {
            const int v0 = (t >= off) ? s[t - off] : 0;
            const int v1 = s[t + 256 - off];
            __syncthreads();
            s[t] += v0;
            s[t + 256] += v1;
            __syncthreads();
        }
        const int fr = fr0 + t;
        const int total = s[511];
        int idx = -1;
        if (fr < total) {
            int lo = 0, hi = LQ;
            while (lo < hi) {
                const int mid = (lo + hi) >> 1;
                if (s[mid] <= fr) lo = mid + 1; else hi = mid;
            }
            idx = min(lo, LQ - 1);
        }
        g_fidx[b * M + fr] = idx;
    }
}

__device__ __forceinline__ void mma_f16(float c[4], unsigned a0, unsigned a1,
                                        unsigned a2, unsigned a3,
                                        unsigned b0, unsigned b1)
{
    asm volatile(
        "mma.sync.aligned.m16n8k16.row.col.f32.f16.f16.f32 "
        "{%0,%1,%2,%3}, {%4,%5,%6,%7}, {%8,%9}, {%0,%1,%2,%3};"
        : "+f"(c[0]), "+f"(c[1]), "+f"(c[2]), "+f"(c[3])
        : "r"(a0), "r"(a1), "r"(a2), "r"(a3), "r"(b0), "r"(b1));
}

__device__ __forceinline__ void cp16(unsigned dst, const void* src, bool p)
{
    const int sz = p ? 16 : 0;
    asm volatile("cp.async.cg.shared.global [%0], [%1], 16, %2;\n"
                 :: "r"(dst), "l"(src), "r"(sz));
}

// ---------------------------------------------------------------------------
// Conv fp16 mma: CTA tile 64x64, BK=32, 128 threads, 4 warps 2x2 (warp 32x32),
// 3-stage cp.async, 6 CTAs/SM. Blocks >= GEMM_BLOCKS: expand (pure copy via
// precomputed g_fidx).
// ---------------------------------------------------------------------------
__global__ __launch_bounds__(128, 6) void conv_expand_kernel(
    const __half* __restrict__ Asrc, const __half* __restrict__ Wr,
    const float* __restrict__ bias, float* __restrict__ Y,
    const float* __restrict__ X, float* __restrict__ out,
    int M, int exp_base)
{
    if (blockIdx.x >= GEMM_BLOCKS) {
        // ---------------- expand: 8 frames = 768 float4, flat over 128 thr ----
        const int g   = blockIdx.x - GEMM_BLOCKS + exp_base;
        const int gpb = M >> 3;
        const int b   = g / gpb;
        const int fg  = g - b * gpb;
        const int* fi = g_fidx + b * M + fg * 8;
        float4* obase = (float4*)(out + (size_t)b * M * DD) + (size_t)fg * 768;
        #pragma unroll
        for (int i = 0; i < 6; ++i) {
            const int idx  = i * 128 + threadIdx.x;    // 0..767
            const int fr8  = idx / 96;
            const int lane = idx - fr8 * 96;
            const int sidx = __ldg(&fi[fr8]);
            if (sidx < 0) {
                __stcs(&obase[idx], make_float4(0.f, 0.f, 0.f, 0.f));
            } else {
                const float4* src = (const float4*)(X + ((size_t)b * LQ + sidx) * DD);
                __stcs(&obase[idx], __ldg(&src[lane]));
            }
        }
        return;
    }

    // ---------------- conv ----------------
    extern __shared__ __half smh[];
    __half* As = smh;                          // [STAGES][64][RSH]
    __half* Bs = smh + STAGES * 64 * RSH;      // [STAGES][64][RSH]

    const int m0 = (blockIdx.x & 255) * 64;
    const int f0 = (blockIdx.x >> 8) * 64;
    const int t  = threadIdx.x;
    const int lane = t & 31, grp = lane >> 2, tig = lane & 3;
    const int warp = t >> 5;
    const int m_base = (warp & 1) * 32;
    const int n_base = (warp >> 1) * 32;

    const int lrow = t >> 2;            // 0..31
    const int c    = t & 3;             // 16B chunk within 64B of data

    int bA[2], lA[2];
    #pragma unroll
    for (int rr = 0; rr < 2; ++rr) {
        const int m = m0 + lrow + rr * 32;
        bA[rr] = m >> 9;
        lA[rr] = m & 511;
    }

    const unsigned aAd0 = (unsigned)__cvta_generic_to_shared(&As[lrow * RSH + c * 8]);
    const unsigned bAd0 = (unsigned)__cvta_generic_to_shared(&Bs[lrow * RSH + c * 8]);
    const unsigned STB   = 64 * RSH * 2;    // 6144 B per stage (A or B)
    const unsigned ROW32 = 32 * RSH * 2;    // 3072

    const __half* wr0 = Wr + (size_t)(f0 + lrow) * KDIM + c * 8;
    const __half* wr1 = Wr + (size_t)(f0 + lrow + 32) * KDIM + c * 8;

    float acc[2][4][4] = {};

    auto load_tile = [&](int it, int st) {
        const int kk0  = it * 32;
        const int kseg = (kk0 >= 384) + (kk0 >= 768);
        const int off  = kk0 - kseg * DD + c * 8;
        #pragma unroll
        for (int rr = 0; rr < 2; ++rr) {
            const int l2 = lA[rr] + kseg - 1;
            const bool v = (l2 >= 0) & (l2 < LQ);
            const __half* sa = Asrc + ((size_t)(bA[rr] << 9) + (v ? l2 : 0)) * DD + off;
            cp16(aAd0 + st * STB + rr * ROW32, sa, v);
        }
        cp16(bAd0 + st * STB,         wr0 + kk0, true);
        cp16(bAd0 + st * STB + ROW32, wr1 + kk0, true);
    };

    load_tile(0, 0);
    asm volatile("cp.async.commit_group;");
    load_tile(1, 1);
    asm volatile("cp.async.commit_group;");
    asm volatile("cp.async.wait_group 1;");
    __syncthreads();

    const int NIT = KDIM / 32;   // 36
    int st_next = 2, buf = 0;
    for (int it = 0; it < NIT; ++it) {
        if (it + 2 < NIT) load_tile(it + 2, st_next);
        asm volatile("cp.async.commit_group;");
        if (++st_next == STAGES) st_next = 0;

        const __half* Ab = As + buf * 64 * RSH;
        const __half* Bb = Bs + buf * 64 * RSH;
        #pragma unroll
        for (int ks = 0; ks < 2; ++ks) {
            const int pch = ks * 16 + tig * 4;
            uint2 bf[4];
            #pragma unroll
            for (int nt = 0; nt < 4; ++nt)
                bf[nt] = *(const uint2*)&Bb[(n_base + nt * 8 + grp) * RSH + pch];
            #pragma unroll
            for (int mt = 0; mt < 2; ++mt) {
                const int ar = m_base + mt * 16 + grp;
                const uint2 ua = *(const uint2*)&Ab[ar * RSH + pch];
                const uint2 ub = *(const uint2*)&Ab[(ar + 8) * RSH + pch];
                #pragma unroll
                for (int nt = 0; nt < 4; ++nt)
                    mma_f16(acc[mt][nt], ua.x, ub.x, ua.y, ub.y,
                            bf[nt].x, bf[nt].y);
            }
        }
        if (++buf == STAGES) buf = 0;

        asm volatile("cp.async.wait_group 1;");
        __syncthreads();
    }

    #pragma unroll
    for (int mt = 0; mt < 2; ++mt) {
        const int mrow = m0 + m_base + mt * 16 + grp;
        #pragma unroll
        for (int nt = 0; nt < 4; ++nt) {
            const int fc = f0 + n_base + nt * 8 + 2 * tig;
            const float b0v = bias[fc], b1v = bias[fc + 1];
            float2 r0 = make_float2(acc[mt][nt][0] + b0v, acc[mt][nt][1] + b1v);
            float2 r1 = make_float2(acc[mt][nt][2] + b0v, acc[mt][nt][3] + b1v);
            *(float2*)&Y[(size_t)mrow * FF + fc] = r0;
            *(float2*)&Y[(size_t)(mrow + 8) * FF + fc] = r1;
        }
    }
}

// ---------------------------------------------------------------------------
// (sum, sumsq) reduction over 128 threads of one row; sh8 = 8 floats per row.
__device__ __forceinline__ float2 row_reduce2(float s, float q, float* sh8)
{
    __syncthreads();
    const int lane = threadIdx.x & 31;
    const int w    = threadIdx.x >> 5;
    #pragma unroll
    for (int o = 16; o > 0; o >>= 1) {
        s += __shfl_down_sync(0xffffffffu, s, o);
        q += __shfl_down_sync(0xffffffffu, q, o);
    }
    if (lane == 0) { sh8[w] = s; sh8[4 + w] = q; }
    __syncthreads();
    if (threadIdx.x == 0) {
        sh8[0] = sh8[0] + sh8[1] + sh8[2] + sh8[3];
        sh8[4] = sh8[4] + sh8[5] + sh8[6] + sh8[7];
    }
    __syncthreads();
    return make_float2(sh8[0], sh8[4]);
}

// LN+ReLU -> fp16 permuted; 4 rows per block (threadIdx.y), 128 thr per row.
__global__ __launch_bounds__(512) void ln_relu_kernel(
    const float* __restrict__ In, const float* __restrict__ gam,
    const float* __restrict__ bet, __half* __restrict__ Out)
{
    __shared__ float sh[4][8];
    const int row = blockIdx.x * 4 + threadIdx.y;
    const int t   = threadIdx.x;
    const float* p = In + (size_t)row * FF;
    float v0 = p[t], v1 = p[t + 128], v2 = p[t + 256];
    float2 r = row_reduce2(v0 + v1 + v2, v0 * v0 + v1 * v1 + v2 * v2,
                           sh[threadIdx.y]);
    const float mu  = r.x * (1.0f / FF);
    const float var = r.y * (1.0f / FF) - mu * mu;
    const float rs  = rsqrtf(var + LN_EPS);
    __half* o = Out + (size_t)row * FF;
    float v[3] = {v0, v1, v2};
    #pragma unroll
    for (int i = 0; i < 3; i++) {
        const int f = t + i * 128;
        const float h = fmaxf((v[i] - mu) * rs * gam[f] + bet[f], 0.0f);
        const int blk = f >> 4, j = f & 15;
        o[(blk << 4) + perm16h(j)] = __float2half_rn(h);
    }
}

__global__ __launch_bounds__(512) void ln_linear_kernel(
    const float* __restrict__ In, const float* __restrict__ gam,
    const float* __restrict__ bet, const float* __restrict__ lw,
    const float* __restrict__ lb, float* __restrict__ dur)
{
    __shared__ float sh[4][8];
    const int row = blockIdx.x * 4 + threadIdx.y;
    const int t   = threadIdx.x;
    const float* p = In + (size_t)row * FF;
    float v0 = p[t], v1 = p[t + 128], v2 = p[t + 256];
    float2 r = row_reduce2(v0 + v1 + v2, v0 * v0 + v1 * v1 + v2 * v2,
                           sh[threadIdx.y]);
    const float mu  = r.x * (1.0f / FF);
    const float var = r.y * (1.0f / FF) - mu * mu;
    const float rs  = rsqrtf(var + LN_EPS);
    float v[3] = {v0, v1, v2};
    float acc = 0.0f;
    #pragma unroll
    for (int i = 0; i < 3; i++) {
        const int f = t + i * 128;
        float h = fmaxf((v[i] - mu) * rs * gam[f] + bet[f], 0.0f);
        acc += h * lw[f];
    }
    float2 r2 = row_reduce2(acc, 0.0f, sh[threadIdx.y]);
    if (t == 0) dur[row] = fmaxf(r2.x + lb[0], 0.0f);
}

// ---------------------------------------------------------------------------
extern "C" void kernel_launch(void* const* d_in, const int* in_sizes, int n_in,
                              void* d_out, int out_size)
{
    const float* x     = (const float*)d_in[0];
    const float* c1_w  = (const float*)d_in[1];
    const float* c1_b  = (const float*)d_in[2];
    const float* ln1_g = (const float*)d_in[3];
    const float* ln1_b = (const float*)d_in[4];
    const float* c2_w  = (const float*)d_in[5];
    const float* c2_b  = (const float*)d_in[6];
    const float* ln2_g = (const float*)d_in[7];
    const float* ln2_b = (const float*)d_in[8];
    const float* lin_w = (const float*)d_in[9];
    const float* lin_b = (const float*)d_in[10];
    const int*   target= (const int*)d_in[11];

    const int M = (out_size - BB * LQ) / (BB * DD);

    float*  buf1;  cudaGetSymbolAddress((void**)&buf1,  g_buf1);
    __half* buf2h; cudaGetSymbolAddress((void**)&buf2h, g_buf2h);
    __half* xph;   cudaGetSymbolAddress((void**)&xph,   g_xph);
    __half* w1rh;  cudaGetSymbolAddress((void**)&w1rh,  g_w1rh);
    __half* w2rh;  cudaGetSymbolAddress((void**)&w2rh,  g_w2rh);

    float* out_expand = (float*)d_out;
    float* out_dur    = (float*)d_out + (size_t)BB * M * DD;

    const int smem_bytes = STAGES * (64 + 64) * RSH * 2;  // 36864
    cudaFuncSetAttribute(conv_expand_kernel,
                         cudaFuncAttributeMaxDynamicSharedMemorySize, smem_bytes);

    const int nfi       = BB * (M >> 8);   // frame-index blocks (512 for M=4096)
    const int exp_total = BB * (M >> 3);   // 16384
    const int exp_half  = exp_total / 2;

    prep_all_kernel<<<NPX2 + NWR + nfi, 256>>>(x, xph, c1_w, w1rh, c2_w, w2rh,
                                               target, M);
    conv_expand_kernel<<<GEMM_BLOCKS + exp_half, 128, smem_bytes>>>(
        xph, w1rh, c1_b, buf1, x, out_expand, M, 0);
    ln_relu_kernel<<<MROWS / 4, dim3(128, 4)>>>(buf1, ln1_g, ln1_b, buf2h);
    conv_expand_kernel<<<GEMM_BLOCKS + (exp_total - exp_half), 128, smem_bytes>>>(
        buf2h, w2rh, c2_b, buf1, x, out_expand, M, exp_half);
    ln_linear_kernel<<<MROWS / 4, dim3(128, 4)>>>(buf1, ln2_g, ln2_b, lin_w, lin_b, out_dur);
}

// round 13
// speedup vs baseline: 1.8500x; 1.0108x over previous
#include <cuda_runtime.h>
#include <cuda_fp16.h>
#include <math.h>

#define BB   32
#define LQ   512
#define DD   384
#define FF   384
#define MROWS (BB*LQ)      // 16384
#define KDIM  (DD*3)       // 1152 halves
#define LN_EPS 1e-5f
#define STAGES 3
#define RSH 48             // smem row stride in halves (96 B)
#define GEMM_BLOCKS ((MROWS/64)*(FF/128))   // 768
#define NPX2 (MROWS*DD/2/256)               // 12288
#define NWR (FF*2)                          // 768

// Scratch (no allocations allowed).
__device__ float  g_buf1[(size_t)MROWS * FF];
__device__ __half g_buf2h[(size_t)MROWS * FF];
__device__ __half g_xph [(size_t)MROWS * DD];
__device__ __half g_w1rh[(size_t)FF * KDIM];
__device__ __half g_w2rh[(size_t)FF * KDIM];
__device__ int    g_fidx[BB * 8192];        // frame -> source phoneme (-1 = pad)

// Half-pair permutation within each 16-half block.
__device__ __forceinline__ int perm16h(int j)
{
    const int p = j >> 1;
    const int pos = (p < 4) ? 2 * p : 2 * (p - 4) + 1;
    return pos * 2 + (j & 1);
}

// ---------------------------------------------------------------------------
// Fused prep (unchanged from R12).
// ---------------------------------------------------------------------------
__global__ __launch_bounds__(256) void prep_all_kernel(
    const float* __restrict__ x, __half* __restrict__ xp,
    const float* __restrict__ W1, __half* __restrict__ Wr1,
    const float* __restrict__ W2, __half* __restrict__ Wr2,
    const int* __restrict__ target, int M)
{
    const int bidx = blockIdx.x;
    const int t = threadIdx.x;

    if (bidx < NPX2) {
        const int idx2 = bidx * 256 + t;
        const int row  = idx2 / 192;
        const int pc   = idx2 - row * 192;
        const int blk  = pc >> 3, p = pc & 7;
        const int pos  = (p < 4) ? 2 * p : 2 * (p - 4) + 1;
        const float2 v = *(const float2*)&x[(size_t)row * DD + (blk << 4) + p * 2];
        *(__half2*)&xp[(size_t)row * DD + (blk << 4) + pos * 2] =
            __floats2half2_rn(v.x, v.y);
    } else if (bidx < NPX2 + NWR) {
        const int r2 = bidx - NPX2;
        const float* W  = (r2 >= FF) ? W2 : W1;
        __half*     Wr = (r2 >= FF) ? Wr2 : Wr1;
        const int f = (r2 >= FF) ? r2 - FF : r2;
        for (int i = t; i < KDIM; i += 256) {
            const int kseg = i / DD;
            const int r    = i - kseg * DD;
            const int blk  = r >> 4, j = r & 15;
            const int dst  = kseg * DD + (blk << 4) + perm16h(j);
            Wr[(size_t)f * KDIM + dst] =
                __float2half_rn(W[(size_t)f * KDIM + (blk * 16 + j) * 3 + kseg]);
        }
    } else {
        __shared__ int s[512];
        const int fb  = bidx - (NPX2 + NWR);
        const int bpB = M >> 8;
        const int b   = fb / bpB;
        const int fr0 = (fb - b * bpB) * 256;
        s[t]       = target[b * LQ + t];
        s[t + 256] = target[b * LQ + t + 256];
        __syncthreads();
        for (int off = 1; off < 512; off <<= 1) {
            const int v0 = (t >= off) ? s[t - off] : 0;
            const int v1 = s[t + 256 - off];
            __syncthreads();
            s[t] += v0;
            s[t + 256] += v1;
            __syncthreads();
        }
        const int fr = fr0 + t;
        const int total = s[511];
        int idx = -1;
        if (fr < total) {
            int lo = 0, hi = LQ;
            while (lo < hi) {
                const int mid = (lo + hi) >> 1;
                if (s[mid] <= fr) lo = mid + 1; else hi = mid;
            }
            idx = min(lo, LQ - 1);
        }
        g_fidx[b * M + fr] = idx;
    }
}

__device__ __forceinline__ void mma_f16(float c[4], unsigned a0, unsigned a1,
                                        unsigned a2, unsigned a3,
                                        unsigned b0, unsigned b1)
{
    asm volatile(
        "mma.sync.aligned.m16n8k16.row.col.f32.f16.f16.f32 "
        "{%0,%1,%2,%3}, {%4,%5,%6,%7}, {%8,%9}, {%0,%1,%2,%3};"
        : "+f"(c[0]), "+f"(c[1]), "+f"(c[2]), "+f"(c[3])
        : "r"(a0), "r"(a1), "r"(a2), "r"(a3), "r"(b0), "r"(b1));
}

__device__ __forceinline__ void cp16(unsigned dst, const void* src, bool p)
{
    const int sz = p ? 16 : 0;
    asm volatile("cp.async.cg.shared.global [%0], [%1], 16, %2;\n"
                 :: "r"(dst), "l"(src), "r"(sz));
}

// ---------------------------------------------------------------------------
// Conv fp16 mma: CTA tile 64(M) x 128(N), BK=32, 128 threads, 4 warps 2x2
// (warp tile 32x64 -> 32 MMA per 24 LDS.64 per iter), 3-stage cp.async,
// 4 CTAs/SM. Blocks >= GEMM_BLOCKS: expand via precomputed g_fidx.
// ---------------------------------------------------------------------------
__global__ __launch_bounds__(128, 4) void conv_expand_kernel(
    const __half* __restrict__ Asrc, const __half* __restrict__ Wr,
    const float* __restrict__ bias, float* __restrict__ Y,
    const float* __restrict__ X, float* __restrict__ out,
    int M, int exp_base)
{
    if (blockIdx.x >= GEMM_BLOCKS) {
        const int g   = blockIdx.x - GEMM_BLOCKS + exp_base;
        const int gpb = M >> 3;
        const int b   = g / gpb;
        const int fg  = g - b * gpb;
        const int* fi = g_fidx + b * M + fg * 8;
        float4* obase = (float4*)(out + (size_t)b * M * DD) + (size_t)fg * 768;
        #pragma unroll
        for (int i = 0; i < 6; ++i) {
            const int idx  = i * 128 + threadIdx.x;
            const int fr8  = idx / 96;
            const int lane = idx - fr8 * 96;
            const int sidx = __ldg(&fi[fr8]);
            if (sidx < 0) {
                __stcs(&obase[idx], make_float4(0.f, 0.f, 0.f, 0.f));
            } else {
                const float4* src = (const float4*)(X + ((size_t)b * LQ + sidx) * DD);
                __stcs(&obase[idx], __ldg(&src[lane]));
            }
        }
        return;
    }

    // ---------------- conv ----------------
    extern __shared__ __half smh[];
    __half* As = smh;                          // [STAGES][64][RSH]
    __half* Bs = smh + STAGES * 64 * RSH;      // [STAGES][128][RSH]

    const int m0 = (blockIdx.x & 255) * 64;    // 256 m-tiles
    const int f0 = (blockIdx.x >> 8) * 128;    // 3 f-tiles
    const int t  = threadIdx.x;
    const int lane = t & 31, grp = lane >> 2, tig = lane & 3;
    const int warp = t >> 5;
    const int m_base = (warp & 1) * 32;
    const int n_base = (warp >> 1) * 64;

    const int lrow = t >> 2;            // 0..31
    const int c    = t & 3;

    int bA[2], lA[2];
    #pragma unroll
    for (int rr = 0; rr < 2; ++rr) {
        const int m = m0 + lrow + rr * 32;
        bA[rr] = m >> 9;
        lA[rr] = m & 511;
    }

    const unsigned aAd0 = (unsigned)__cvta_generic_to_shared(&As[lrow * RSH + c * 8]);
    const unsigned bAd0 = (unsigned)__cvta_generic_to_shared(&Bs[lrow * RSH + c * 8]);
    const unsigned STB_A = 64 * RSH * 2;    // 6144
    const unsigned STB_B = 128 * RSH * 2;   // 12288
    const unsigned ROW32 = 32 * RSH * 2;    // 3072

    const __half* wrp[4];
    #pragma unroll
    for (int rr = 0; rr < 4; ++rr)
        wrp[rr] = Wr + (size_t)(f0 + lrow + rr * 32) * KDIM + c * 8;

    float acc[2][8][4] = {};

    auto load_tile = [&](int it, int st) {
        const int kk0  = it * 32;
        const int kseg = (kk0 >= 384) + (kk0 >= 768);
        const int off  = kk0 - kseg * DD + c * 8;
        #pragma unroll
        for (int rr = 0; rr < 2; ++rr) {
            const int l2 = lA[rr] + kseg - 1;
            const bool v = (l2 >= 0) & (l2 < LQ);
            const __half* sa = Asrc + ((size_t)(bA[rr] << 9) + (v ? l2 : 0)) * DD + off;
            cp16(aAd0 + st * STB_A + rr * ROW32, sa, v);
        }
        #pragma unroll
        for (int rr = 0; rr < 4; ++rr)
            cp16(bAd0 + st * STB_B + rr * ROW32, wrp[rr] + kk0, true);
    };

    load_tile(0, 0);
    asm volatile("cp.async.commit_group;");
    load_tile(1, 1);
    asm volatile("cp.async.commit_group;");
    asm volatile("cp.async.wait_group 1;");
    __syncthreads();

    const int NIT = KDIM / 32;   // 36
    int st_next = 2, buf = 0;
    for (int it = 0; it < NIT; ++it) {
        if (it + 2 < NIT) load_tile(it + 2, st_next);
        asm volatile("cp.async.commit_group;");
        if (++st_next == STAGES) st_next = 0;

        const __half* Ab = As + buf * 64 * RSH;
        const __half* Bb = Bs + buf * 128 * RSH;
        #pragma unroll
        for (int ks = 0; ks < 2; ++ks) {
            const int pch = ks * 16 + tig * 4;
            uint2 bf[8];
            #pragma unroll
            for (int nt = 0; nt < 8; ++nt)
                bf[nt] = *(const uint2*)&Bb[(n_base + nt * 8 + grp) * RSH + pch];
            #pragma unroll
            for (int mt = 0; mt < 2; ++mt) {
                const int ar = m_base + mt * 16 + grp;
                const uint2 ua = *(const uint2*)&Ab[ar * RSH + pch];
                const uint2 ub = *(const uint2*)&Ab[(ar + 8) * RSH + pch];
                #pragma unroll
                for (int nt = 0; nt < 8; ++nt)
                    mma_f16(acc[mt][nt], ua.x, ub.x, ua.y, ub.y,
                            bf[nt].x, bf[nt].y);
            }
        }
        if (++buf == STAGES) buf = 0;

        asm volatile("cp.async.wait_group 1;");
        __syncthreads();
    }

    #pragma unroll
    for (int mt = 0; mt < 2; ++mt) {
        const int mrow = m0 + m_base + mt * 16 + grp;
        #pragma unroll
        for (int nt = 0; nt < 8; ++nt) {
            const int fc = f0 + n_base + nt * 8 + 2 * tig;
            const float b0v = bias[fc], b1v = bias[fc + 1];
            float2 r0 = make_float2(acc[mt][nt][0] + b0v, acc[mt][nt][1] + b1v);
            float2 r1 = make_float2(acc[mt][nt][2] + b0v, acc[mt][nt][3] + b1v);
            *(float2*)&Y[(size_t)mrow * FF + fc] = r0;
            *(float2*)&Y[(size_t)(mrow + 8) * FF + fc] = r1;
        }
    }
}

// ---------------------------------------------------------------------------
__device__ __forceinline__ float2 row_reduce2(float s, float q, float* sh8)
{
    __syncthreads();
    const int lane = threadIdx.x & 31;
    const int w    = threadIdx.x >> 5;
    #pragma unroll
    for (int o = 16; o > 0; o >>= 1) {
        s += __shfl_down_sync(0xffffffffu, s, o);
        q += __shfl_down_sync(0xffffffffu, q, o);
    }
    if (lane == 0) { sh8[w] = s; sh8[4 + w] = q; }
    __syncthreads();
    if (threadIdx.x == 0) {
        sh8[0] = sh8[0] + sh8[1] + sh8[2] + sh8[3];
        sh8[4] = sh8[4] + sh8[5] + sh8[6] + sh8[7];
    }
    __syncthreads();
    return make_float2(sh8[0], sh8[4]);
}

__global__ __launch_bounds__(512) void ln_relu_kernel(
    const float* __restrict__ In, const float* __restrict__ gam,
    const float* __restrict__ bet, __half* __restrict__ Out)
{
    __shared__ float sh[4][8];
    const int row = blockIdx.x * 4 + threadIdx.y;
    const int t   = threadIdx.x;
    const float* p = In + (size_t)row * FF;
    float v0 = p[t], v1 = p[t + 128], v2 = p[t + 256];
    float2 r = row_reduce2(v0 + v1 + v2, v0 * v0 + v1 * v1 + v2 * v2,
                           sh[threadIdx.y]);
    const float mu  = r.x * (1.0f / FF);
    const float var = r.y * (1.0f / FF) - mu * mu;
    const float rs  = rsqrtf(var + LN_EPS);
    __half* o = Out + (size_t)row * FF;
    float v[3] = {v0, v1, v2};
    #pragma unroll
    for (int i = 0; i < 3; i++) {
        const int f = t + i * 128;
        const float h = fmaxf((v[i] - mu) * rs * gam[f] + bet[f], 0.0f);
        const int blk = f >> 4, j = f & 15;
        o[(blk << 4) + perm16h(j)] = __float2half_rn(h);
    }
}

__global__ __launch_bounds__(512) void ln_linear_kernel(
    const float* __restrict__ In, const float* __restrict__ gam,
    const float* __restrict__ bet, const float* __restrict__ lw,
    const float* __restrict__ lb, float* __restrict__ dur)
{
    __shared__ float sh[4][8];
    const int row = blockIdx.x * 4 + threadIdx.y;
    const int t   = threadIdx.x;
    const float* p = In + (size_t)row * FF;
    float v0 = p[t], v1 = p[t + 128], v2 = p[t + 256];
    float2 r = row_reduce2(v0 + v1 + v2, v0 * v0 + v1 * v1 + v2 * v2,
                           sh[threadIdx.y]);
    const float mu  = r.x * (1.0f / FF);
    const float var = r.y * (1.0f / FF) - mu * mu;
    const float rs  = rsqrtf(var + LN_EPS);
    float v[3] = {v0, v1, v2};
    float acc = 0.0f;
    #pragma unroll
    for (int i = 0; i < 3; i++) {
        const int f = t + i * 128;
        float h = fmaxf((v[i] - mu) * rs * gam[f] + bet[f], 0.0f);
        acc += h * lw[f];
    }
    float2 r2 = row_reduce2(acc, 0.0f, sh[threadIdx.y]);
    if (t == 0) dur[row] = fmaxf(r2.x + lb[0], 0.0f);
}

// ---------------------------------------------------------------------------
extern "C" void kernel_launch(void* const* d_in, const int* in_sizes, int n_in,
                              void* d_out, int out_size)
{
    const float* x     = (const float*)d_in[0];
    const float* c1_w  = (const float*)d_in[1];
    const float* c1_b  = (const float*)d_in[2];
    const float* ln1_g = (const float*)d_in[3];
    const float* ln1_b = (const float*)d_in[4];
    const float* c2_w  = (const float*)d_in[5];
    const float* c2_b  = (const float*)d_in[6];
    const float* ln2_g = (const float*)d_in[7];
    const float* ln2_b = (const float*)d_in[8];
    const float* lin_w = (const float*)d_in[9];
    const float* lin_b = (const float*)d_in[10];
    const int*   target= (const int*)d_in[11];

    const int M = (out_size - BB * LQ) / (BB * DD);

    float*  buf1;  cudaGetSymbolAddress((void**)&buf1,  g_buf1);
    __half* buf2h; cudaGetSymbolAddress((void**)&buf2h, g_buf2h);
    __half* xph;   cudaGetSymbolAddress((void**)&xph,   g_xph);
    __half* w1rh;  cudaGetSymbolAddress((void**)&w1rh,  g_w1rh);
    __half* w2rh;  cudaGetSymbolAddress((void**)&w2rh,  g_w2rh);

    float* out_expand = (float*)d_out;
    float* out_dur    = (float*)d_out + (size_t)BB * M * DD;

    const int smem_bytes = STAGES * (64 + 128) * RSH * 2;  // 55296
    cudaFuncSetAttribute(conv_expand_kernel,
                         cudaFuncAttributeMaxDynamicSharedMemorySize, smem_bytes);

    const int nfi       = BB * (M >> 8);
    const int exp_total = BB * (M >> 3);
    const int exp_half  = exp_total / 2;

    prep_all_kernel<<<NPX2 + NWR + nfi, 256>>>(x, xph, c1_w, w1rh, c2_w, w2rh,
                                               target, M);
    conv_expand_kernel<<<GEMM_BLOCKS + exp_half, 128, smem_bytes>>>(
        xph, w1rh, c1_b, buf1, x, out_expand, M, 0);
    ln_relu_kernel<<<MROWS / 4, dim3(128, 4)>>>(buf1, ln1_g, ln1_b, buf2h);
    conv_expand_kernel<<<GEMM_BLOCKS + (exp_total - exp_half), 128, smem_bytes>>>(
        buf2h, w2rh, c2_b, buf1, x, out_expand, M, exp_half);
    ln_linear_kernel<<<MROWS / 4, dim3(128, 4)>>>(buf1, ln2_g, ln2_b, lin_w, lin_b, out_dur);
}